// round 2
// baseline (speedup 1.0000x reference)
#include <cuda_runtime.h>

#define BV 2
#define CV 3
#define HV 512
#define WV 512
#define NPIX (HV*WV)
#define CN (CV*NPIX)
#define BCN (BV*CN)
#define GH 64
#define GW 64
#define NBIN 9
#define NGRID (BV*CV*GH*GW*NBIN*2)
#define EPSF 1e-8f
#define CG_TOL 1e-4f
#define NRED 256
#define CTX 32
#define CTY 16
#define NTHR (CTX*CTY)

// ---------------- scratch (device globals; no allocation) ----------------
__device__ float g_x[BCN];
__device__ float g_r[BCN];
__device__ float g_p[BCN];
__device__ float g_t[BCN];
__device__ float g_u[BCN];
__device__ float g_d[BV*6*CN];
__device__ float g_v[BV*5*CN];
__device__ float g_Rp[BV*5*CN];
__device__ float g_tgt[BV*5*CN];
__device__ float g_gridA[NGRID];
__device__ float g_gridB[NGRID];
__device__ float g_partN[BV*NRED];
__device__ float g_partD[BV*NRED];
__device__ float g_partR[BV*NRED];
__device__ float g_alpha[BV];
__device__ float g_beta[BV];
__device__ float g_rn[BV];
__device__ float g_r0[BV];
__device__ int   g_done[BV];
__device__ int   g_pfz[BV];

__device__ __forceinline__ float powx(float a, float e){
    if (e == 0.0f) return 1.0f;
    if (e == 1.0f) return a;
    return powf(a, e);
}
__device__ __forceinline__ float sgnf(float v){
    return (v > 0.f) ? 1.f : ((v < 0.f) ? -1.f : 0.f);
}

// ---------------- elementwise ----------------
__global__ void k_copy(float* __restrict__ dst, const float* __restrict__ src, int n){
    int i = blockIdx.x*blockDim.x + threadIdx.x;
    if (i < n) dst[i] = src[i];
}

__global__ void k_axpy_x(){  // x += alpha*p  (gated on done)
    int i = blockIdx.x*blockDim.x + threadIdx.x;
    if (i >= BCN) return;
    int b = i / CN;
    if (g_done[b]) return;
    g_x[i] = fmaf(g_alpha[b], g_p[i], g_x[i]);
}

__global__ void k_updp(){    // p = r + beta*p  (gated on pfreeze)
    int i = blockIdx.x*blockDim.x + threadIdx.x;
    if (i >= BCN) return;
    int b = i / CN;
    if (g_pfz[b]) return;
    g_p[i] = fmaf(g_beta[b], g_p[i], g_r[i]);
}

// ---------------- 15x15 cross-correlation (optionally minus `sub`) ----------------
__global__ void __launch_bounds__(NTHR)
k_conv15(const float* __restrict__ src, float* __restrict__ dst,
         const float* __restrict__ kern, const float* __restrict__ sub,
         int gated)
{
    int z = blockIdx.z; int b = z / CV;
    if (gated && g_done[b]) return;
    __shared__ float tile[CTY+14][CTX+14];
    __shared__ float sk[225];
    const float* sp = src + z*NPIX;
    int x0 = blockIdx.x*CTX - 7, y0 = blockIdx.y*CTY - 7;
    int tid = threadIdx.y*CTX + threadIdx.x;
    for (int i = tid; i < (CTY+14)*(CTX+14); i += NTHR){
        int ty = i/(CTX+14), tx = i - ty*(CTX+14);
        int gy = y0+ty, gx = x0+tx;
        tile[ty][tx] = (gy>=0 && gy<HV && gx>=0 && gx<WV) ? sp[gy*WV+gx] : 0.f;
    }
    const float* kb = kern + b*225;
    for (int i = tid; i < 225; i += NTHR) sk[i] = kb[i];
    __syncthreads();
    float acc = 0.f;
    #pragma unroll
    for (int u = 0; u < 15; u++){
        #pragma unroll
        for (int v = 0; v < 15; v++)
            acc = fmaf(sk[u*15+v], tile[threadIdx.y+u][threadIdx.x+v], acc);
    }
    int gy = blockIdx.y*CTY + threadIdx.y, gx = blockIdx.x*CTX + threadIdx.x;
    int oi = z*NPIX + gy*WV + gx;
    if (sub) acc -= sub[oi];
    dst[oi] = acc;
}

// ---------------- bank of 6 5x5 cross-correlations ----------------
__global__ void __launch_bounds__(NTHR)
k_bank6(const float* __restrict__ src, float* __restrict__ dst,
        const float* __restrict__ dks, int stage, int gated)
{
    int z = blockIdx.z; int b = z/CV, c = z - b*CV;
    if (gated && g_done[b]) return;
    __shared__ float tile[CTY+4][CTX+4];
    __shared__ float sk[150];
    const float* sp = src + z*NPIX;
    int x0 = blockIdx.x*CTX - 2, y0 = blockIdx.y*CTY - 2;
    int tid = threadIdx.y*CTX + threadIdx.x;
    for (int i = tid; i < (CTY+4)*(CTX+4); i += NTHR){
        int ty = i/(CTX+4), tx = i - ty*(CTX+4);
        int gy = y0+ty, gx = x0+tx;
        tile[ty][tx] = (gy>=0 && gy<HV && gx>=0 && gx<WV) ? sp[gy*WV+gx] : 0.f;
    }
    const float* kb = dks + stage*150;
    for (int i = tid; i < 150; i += NTHR) sk[i] = kb[i];
    __syncthreads();
    int gy = blockIdx.y*CTY + threadIdx.y, gx = blockIdx.x*CTX + threadIdx.x;
    #pragma unroll
    for (int n = 0; n < 6; n++){
        float acc = 0.f;
        #pragma unroll
        for (int a = 0; a < 5; a++)
            #pragma unroll
            for (int e = 0; e < 5; e++)
                acc = fmaf(sk[n*25+a*5+e], tile[threadIdx.y+a][threadIdx.x+e], acc);
        dst[(b*6+n)*CN + c*NPIX + gy*WV + gx] = acc;
    }
}

// ---------------- adjoint bank6: u = sum_n conv(2*dkw_n*d_n, flip(dk_n)) ----------------
__global__ void __launch_bounds__(NTHR)
k_bank6T(const float* __restrict__ dsrc, float* __restrict__ dst,
         const float* __restrict__ dks, const float* __restrict__ dkw,
         int stage, int gated)
{
    int z = blockIdx.z; int b = z/CV, c = z - b*CV;
    if (gated && g_done[b]) return;
    __shared__ float tile[6][CTY+4][CTX+4];
    __shared__ float sk[150];
    int x0 = blockIdx.x*CTX - 2, y0 = blockIdx.y*CTY - 2;
    int tid = threadIdx.y*CTX + threadIdx.x;
    const float* kb = dks + stage*150;
    for (int i = tid; i < 150; i += NTHR){ int n = i/25, j = i - n*25; sk[i] = kb[n*25 + 24 - j]; }
    const float* wb = dkw + stage*6;
    const int TT = (CTY+4)*(CTX+4);
    for (int i = tid; i < 6*TT; i += NTHR){
        int n = i/TT, rem = i - n*TT;
        int ty = rem/(CTX+4), tx = rem - ty*(CTX+4);
        int gy = y0+ty, gx = x0+tx;
        float v = 0.f;
        if (gy>=0 && gy<HV && gx>=0 && gx<WV)
            v = 2.f*wb[n]*dsrc[(b*6+n)*CN + c*NPIX + gy*WV + gx];
        tile[n][ty][tx] = v;
    }
    __syncthreads();
    float acc = 0.f;
    #pragma unroll
    for (int n = 0; n < 6; n++)
        #pragma unroll
        for (int a = 0; a < 5; a++)
            #pragma unroll
            for (int e = 0; e < 5; e++)
                acc = fmaf(sk[n*25+a*5+e], tile[n][threadIdx.y+a][threadIdx.x+e], acc);
    int gy = blockIdx.y*CTY + threadIdx.y, gx = blockIdx.x*CTX + threadIdx.x;
    dst[z*NPIX + gy*WV + gx] = acc;
}

// ---------------- bank of 5 5x5: out = conv - tgt  OR  shrink(conv, thr) ----------------
__global__ void __launch_bounds__(NTHR)
k_bank5(const float* __restrict__ src, float* __restrict__ dst,
        const float* __restrict__ rks, int stage,
        const float* __restrict__ tgt, const float* __restrict__ thr,
        int gated)
{
    int z = blockIdx.z; int b = z/CV, c = z - b*CV;
    if (gated && g_done[b]) return;
    __shared__ float tile[CTY+4][CTX+4];
    __shared__ float sk[125];
    const float* sp = src + z*NPIX;
    int x0 = blockIdx.x*CTX - 2, y0 = blockIdx.y*CTY - 2;
    int tid = threadIdx.y*CTX + threadIdx.x;
    for (int i = tid; i < (CTY+4)*(CTX+4); i += NTHR){
        int ty = i/(CTX+4), tx = i - ty*(CTX+4);
        int gy = y0+ty, gx = x0+tx;
        tile[ty][tx] = (gy>=0 && gy<HV && gx>=0 && gx<WV) ? sp[gy*WV+gx] : 0.f;
    }
    const float* kb = rks + stage*125;
    for (int i = tid; i < 125; i += NTHR) sk[i] = kb[i];
    __syncthreads();
    int gy = blockIdx.y*CTY + threadIdx.y, gx = blockIdx.x*CTX + threadIdx.x;
    #pragma unroll
    for (int m = 0; m < 5; m++){
        float acc = 0.f;
        #pragma unroll
        for (int a = 0; a < 5; a++)
            #pragma unroll
            for (int e = 0; e < 5; e++)
                acc = fmaf(sk[m*25+a*5+e], tile[threadIdx.y+a][threadIdx.x+e], acc);
        int oi = (b*5+m)*CN + c*NPIX + gy*WV + gx;
        float o = acc;
        if (thr){
            o = sgnf(o)*fmaxf(fabsf(o)-thr[m], 0.f);
        } else if (tgt){
            o -= tgt[oi];
        }
        dst[oi] = o;
    }
}

// ---------------- gradient finisher: r = -(conv15T(u) + bank5T(w*rpow*phi(v))) ----------------
__global__ void __launch_bounds__(NTHR)
k_gradfin(const float* __restrict__ usrc, const float* __restrict__ vsrc,
          float* __restrict__ rdst,
          const float* __restrict__ kern, const float* __restrict__ rks,
          const float* __restrict__ rkw, const float* __restrict__ rpow,
          int stage, int gated)
{
    int z = blockIdx.z; int b = z/CV, c = z - b*CV;
    if (gated && g_done[b]) return;
    __shared__ float su[CTY+14][CTX+14];
    __shared__ float sv[5][CTY+4][CTX+4];
    __shared__ float sk[225];
    __shared__ float srk[125];
    int tid = threadIdx.y*CTX + threadIdx.x;
    const float* kb = kern + b*225;
    for (int i = tid; i < 225; i += NTHR) sk[i] = kb[224 - i];           // flipped 15x15
    const float* rb = rks + stage*125;
    for (int i = tid; i < 125; i += NTHR){ int m = i/25, j = i - m*25; srk[i] = rb[m*25 + 24 - j]; }
    int x0 = blockIdx.x*CTX, y0 = blockIdx.y*CTY;
    const float* up = usrc + z*NPIX;
    for (int i = tid; i < (CTY+14)*(CTX+14); i += NTHR){
        int ty = i/(CTX+14), tx = i - ty*(CTX+14);
        int gy = y0-7+ty, gx = x0-7+tx;
        su[ty][tx] = (gy>=0 && gy<HV && gx>=0 && gx<WV) ? up[gy*WV+gx] : 0.f;
    }
    const float* wv = rkw + stage*5;
    const float* pw = rpow + stage*5;
    const int TT = (CTY+4)*(CTX+4);
    for (int i = tid; i < 5*TT; i += NTHR){
        int m = i/TT, rem = i - m*TT;
        int ty = rem/(CTX+4), tx = rem - ty*(CTX+4);
        int gy = y0-2+ty, gx = x0-2+tx;
        float val = 0.f;
        if (gy>=0 && gy<HV && gx>=0 && gx<WV){
            float vv = vsrc[(b*5+m)*CN + c*NPIX + gy*WV + gx];
            val = wv[m]*pw[m]*sgnf(vv)*powx(fabsf(vv)+EPSF, pw[m]-1.f);
        }
        sv[m][ty][tx] = val;
    }
    __syncthreads();
    float acc = 0.f;
    #pragma unroll
    for (int u = 0; u < 15; u++){
        #pragma unroll
        for (int v2 = 0; v2 < 15; v2++)
            acc = fmaf(sk[u*15+v2], su[threadIdx.y+u][threadIdx.x+v2], acc);
    }
    #pragma unroll
    for (int m = 0; m < 5; m++)
        #pragma unroll
        for (int a = 0; a < 5; a++)
            #pragma unroll
            for (int e = 0; e < 5; e++)
                acc = fmaf(srk[m*25+a*5+e], sv[m][threadIdx.y+a][threadIdx.x+e], acc);
    int gy = blockIdx.y*CTY + threadIdx.y, gx = blockIdx.x*CTX + threadIdx.x;
    rdst[z*NPIX + gy*WV + gx] = -acc;
}

// ---------------- deterministic reductions ----------------
__global__ void k_reduce_dot(const float* __restrict__ a, const float* __restrict__ bb,
                             float* __restrict__ part, int gated)
{
    int b = blockIdx.y;
    if (gated && g_done[b]) return;
    const float* ap = a + b*CN;
    const float* bp = bb ? (bb + b*CN) : ap;
    int t = threadIdx.x;
    float s = 0.f;
    for (int i = blockIdx.x*256 + t; i < CN; i += NRED*256) s = fmaf(ap[i], bp[i], s);
    __shared__ float sh[256];
    sh[t] = s; __syncthreads();
    for (int o = 128; o; o >>= 1){ if (t < o) sh[t] += sh[t+o]; __syncthreads(); }
    if (t == 0) part[b*NRED + blockIdx.x] = sh[0];
}

__global__ void k_reduce_den(const float* __restrict__ dsrc, const float* __restrict__ rpsrc,
                             const float* __restrict__ vsrc,
                             const float* __restrict__ dkw, const float* __restrict__ rkw,
                             const float* __restrict__ rpow, int stage)
{
    int b = blockIdx.y;
    if (g_done[b]) return;
    const float* wb = dkw + stage*6;
    const float* rw = rkw + stage*5;
    const float* pw = rpow + stage*5;
    int t = threadIdx.x;
    float s = 0.f;
    for (int i = blockIdx.x*256 + t; i < CN; i += NRED*256){
        #pragma unroll
        for (int n = 0; n < 6; n++){
            float dv = dsrc[(b*6+n)*CN + i];
            s = fmaf(2.f*wb[n]*dv, dv, s);
        }
        #pragma unroll
        for (int m = 0; m < 5; m++){
            float rv = rpsrc[(b*5+m)*CN + i];
            float vv = vsrc[(b*5+m)*CN + i];
            float w = rw[m]*pw[m]*(pw[m]-1.f)*powx(fabsf(vv)+EPSF, pw[m]-2.f);
            s = fmaf(w*rv, rv, s);
        }
    }
    __shared__ float sh[256];
    sh[t] = s; __syncthreads();
    for (int o = 128; o; o >>= 1){ if (t < o) sh[t] += sh[t+o]; __syncthreads(); }
    if (t == 0) g_partD[b*NRED + blockIdx.x] = sh[0];
}

// ---------------- scalar logic ----------------
__global__ void k_scal_init(){
    int b = blockIdx.x, t = threadIdx.x;
    __shared__ float sh[NRED];
    sh[t] = g_partR[b*NRED + t]; __syncthreads();
    for (int o = 128; o; o >>= 1){ if (t < o) sh[t] += sh[t+o]; __syncthreads(); }
    if (t == 0){ g_rn[b] = sh[0]; g_r0[b] = sh[0]; g_done[b] = 0; g_pfz[b] = 0; }
}

__global__ void k_scal_alpha(){
    int b = blockIdx.x, t = threadIdx.x;
    __shared__ float sn[NRED], sd[NRED];
    sn[t] = g_partN[b*NRED + t];
    sd[t] = g_partD[b*NRED + t];
    __syncthreads();
    for (int o = 128; o; o >>= 1){ if (t < o){ sn[t] += sn[t+o]; sd[t] += sd[t+o]; } __syncthreads(); }
    if (t == 0 && !g_done[b]) g_alpha[b] = sn[0] / (sd[0] + 1e-12f);
}

__global__ void k_scal_beta(){
    int b = blockIdx.x, t = threadIdx.x;
    __shared__ float sh[NRED];
    sh[t] = g_partR[b*NRED + t]; __syncthreads();
    for (int o = 128; o; o >>= 1){ if (t < o) sh[t] += sh[t+o]; __syncthreads(); }
    if (t == 0){
        if (g_done[b]){
            g_pfz[b] = 1;
        } else {
            float nrn = sh[0];
            g_beta[b] = nrn / (g_rn[b] + 1e-20f);
            int conv = (nrn < CG_TOL * g_r0[b]) ? 1 : 0;
            g_rn[b] = nrn;
            g_pfz[b] = conv;
            g_done[b] = conv;
        }
    }
}

// ---------------- bilateral grid ----------------
__global__ void k_splat(const float* __restrict__ x, float* __restrict__ grid){
    int cell = blockIdx.x*blockDim.x + threadIdx.x;
    if (cell >= BV*CV*GH*GW) return;
    int gx = cell & 63;
    int gy = (cell >> 6) & 63;
    int pc = cell >> 12;                 // b*CV + c
    const float* xp = x + pc*NPIX;
    float bv[NBIN], bw[NBIN];
    #pragma unroll
    for (int z = 0; z < NBIN; z++){ bv[z] = 0.f; bw[z] = 0.f; }
    for (int dy = 0; dy < 8; dy++)
        for (int dx = 0; dx < 8; dx++){
            float I = xp[(gy*8+dy)*WV + gx*8+dx];
            float Ic = fminf(fmaxf(I, 0.f), 1.f);
            int zi = (int)rintf(Ic * (float)(NBIN-1));   // round-half-even, matches jnp.round
            zi = max(0, min(NBIN-1, zi));
            bv[zi] += Ic; bw[zi] += 1.f;
        }
    float* gp = grid + (long)cell*NBIN*2;
    #pragma unroll
    for (int z = 0; z < NBIN; z++){ gp[z*2] = bv[z]; gp[z*2+1] = bw[z]; }
}

__global__ void k_convax(const float* __restrict__ in, float* __restrict__ out,
                         const float* __restrict__ f, int taps, int axis)
{
    int e = blockIdx.x*blockDim.x + threadIdx.x;
    if (e >= NGRID) return;
    int r = taps / 2;
    int z = (e >> 1) % NBIN;
    int cellxy = e / (2*NBIN);
    int gx = cellxy & 63;
    int gy = (cellxy >> 6) & 63;
    int coord, extent, stride;
    if (axis == 0){ coord = gy; extent = GH; stride = GW*NBIN*2; }
    else if (axis == 1){ coord = gx; extent = GW; stride = NBIN*2; }
    else { coord = z; extent = NBIN; stride = 2; }
    float s = 0.f;
    for (int t = 0; t < taps; t++){
        int cc = coord + t - r;
        if (cc >= 0 && cc < extent) s = fmaf(f[t], in[e + (cc - coord)*stride], s);
    }
    out[e] = s;
}

__global__ void k_slice(float* __restrict__ x, const float* __restrict__ grid){
    int i = blockIdx.x*blockDim.x + threadIdx.x;
    if (i >= BCN) return;
    int pc = i / NPIX;
    int pix = i - pc*NPIX;
    int y = pix / WV, xx = pix - y*WV;
    float I = x[i];
    float Ic = fminf(fmaxf(I, 0.f), 1.f);
    float yf = (float)y * 0.125f;
    float xf = (float)xx * 0.125f;
    float zf = Ic * (float)(NBIN-1);
    int y0 = max(0, min(GH-1, (int)floorf(yf)));  int y1 = min(y0+1, GH-1);
    float wy = fminf(fmaxf(yf - (float)y0, 0.f), 1.f);
    int x0 = max(0, min(GW-1, (int)floorf(xf)));  int x1 = min(x0+1, GW-1);
    float wx = fminf(fmaxf(xf - (float)x0, 0.f), 1.f);
    int z0 = max(0, min(NBIN-1, (int)floorf(zf))); int z1 = min(z0+1, NBIN-1);
    float wz = fminf(fmaxf(zf - (float)z0, 0.f), 1.f);
    const float* gp = grid + (long)pc*GH*GW*NBIN*2;
    float a0 = 0.f, a1 = 0.f;
    int ys[2]   = {y0, y1};  float wys[2] = {1.f-wy, wy};
    int xs[2]   = {x0, x1};  float wxs[2] = {1.f-wx, wx};
    int zs[2]   = {z0, z1};  float wzs[2] = {1.f-wz, wz};
    for (int a = 0; a < 2; a++)
        for (int bb = 0; bb < 2; bb++)
            for (int cc = 0; cc < 2; cc++){
                float w = wys[a]*wxs[bb]*wzs[cc];
                int idx = (((ys[a]*GW) + xs[bb])*NBIN + zs[cc])*2;
                a0 = fmaf(w, gp[idx], a0);
                a1 = fmaf(w, gp[idx+1], a1);
            }
    x[i] = a0 / (a1 + 1e-8f);
}

// ---------------- host orchestration ----------------
extern "C" void kernel_launch(void* const* d_in, const int* in_sizes, int n_in,
                              void* d_out, int out_size)
{
    const float* blurred = (const float*)d_in[0];
    const float* kern    = (const float*)d_in[1];
    const float* dks     = (const float*)d_in[2];
    const float* dkw     = (const float*)d_in[3];
    const float* rks     = (const float*)d_in[4];
    const float* rkw     = (const float*)d_in[5];
    const float* rpow    = (const float*)d_in[6];
    const float* fs      = (const float*)d_in[7];
    const float* fr      = (const float*)d_in[8];
    const float* thr     = (const float*)d_in[9];
    const int NCG = 5;   // num_cg_iter in this problem instance

    float *px, *pr, *pp, *pt, *pu, *pd, *pv, *pRp, *ptg, *pgA, *pgB, *ppN, *ppR;
    cudaGetSymbolAddress((void**)&px,  g_x);
    cudaGetSymbolAddress((void**)&pr,  g_r);
    cudaGetSymbolAddress((void**)&pp,  g_p);
    cudaGetSymbolAddress((void**)&pt,  g_t);
    cudaGetSymbolAddress((void**)&pu,  g_u);
    cudaGetSymbolAddress((void**)&pd,  g_d);
    cudaGetSymbolAddress((void**)&pv,  g_v);
    cudaGetSymbolAddress((void**)&pRp, g_Rp);
    cudaGetSymbolAddress((void**)&ptg, g_tgt);
    cudaGetSymbolAddress((void**)&pgA, g_gridA);
    cudaGetSymbolAddress((void**)&pgB, g_gridB);
    cudaGetSymbolAddress((void**)&ppN, g_partN);
    cudaGetSymbolAddress((void**)&ppR, g_partR);

    dim3 cb(CTX, CTY);
    dim3 cg(WV/CTX, HV/CTY, BV*CV);
    int EW = (BCN + 255)/256;

    // x = blurred
    k_copy<<<EW,256>>>(px, blurred, BCN);

    auto grad = [&](int stage, const float* tgt, int gated){
        k_conv15<<<cg,cb>>>(px, pt, kern, blurred, gated);                 // t = Kx - b
        k_bank6<<<cg,cb>>>(pt, pd, dks, stage, gated);                     // d = bank6(t)
        k_bank6T<<<cg,cb>>>(pd, pu, dks, dkw, stage, gated);               // u = bank6T(2w d)
        k_bank5<<<cg,cb>>>(px, pv, rks, stage, tgt, nullptr, gated);       // v = bank5(x)-tgt
        k_gradfin<<<cg,cb>>>(pu, pv, pr, kern, rks, rkw, rpow, stage, gated); // r = -grad
    };

    auto cgrun = [&](int stage, const float* tgt){
        grad(stage, tgt, 0);
        k_reduce_dot<<<dim3(NRED,BV),256>>>(pr, nullptr, ppR, 0);
        k_scal_init<<<BV,256>>>();
        k_copy<<<EW,256>>>(pp, pr, BCN);
        for (int it = 0; it < NCG; it++){
            // alpha: num = sum(r*p), den = sum(2w dKp^2) + reg GN term
            k_reduce_dot<<<dim3(NRED,BV),256>>>(pr, pp, ppN, 1);
            k_conv15<<<cg,cb>>>(pp, pt, kern, nullptr, 1);                 // t = Kp
            k_bank6<<<cg,cb>>>(pt, pd, dks, stage, 1);                     // d = dKp
            k_bank5<<<cg,cb>>>(pp, pRp, rks, stage, nullptr, nullptr, 1);  // Rp
            k_reduce_den<<<dim3(NRED,BV),256>>>(pd, pRp, pv, dkw, rkw, rpow, stage);
            k_scal_alpha<<<BV,256>>>();
            k_axpy_x<<<EW,256>>>();                                        // x += alpha p
            grad(stage, tgt, 1);                                           // r = -grad(x)
            k_reduce_dot<<<dim3(NRED,BV),256>>>(pr, nullptr, ppR, 1);
            k_scal_beta<<<BV,256>>>();
            k_updp<<<EW,256>>>();                                          // p = r + beta p
        }
    };

    // Stage 0 CG (targets = 0)
    cgrun(0, nullptr);

    // Bilateral grid filter (per channel, in place on x)
    k_splat<<<(BV*CV*GH*GW + 255)/256, 256>>>(px, pgA);
    int NGE = (NGRID + 255)/256;
    k_convax<<<NGE,256>>>(pgA, pgB, fs, 11, 0);
    k_convax<<<NGE,256>>>(pgB, pgA, fs, 11, 1);
    k_convax<<<NGE,256>>>(pgA, pgB, fr, 5, 2);
    k_slice<<<EW,256>>>(px, pgB);

    // Prior targets from stage-1 reg kernels, then stage-1 CG
    k_bank5<<<cg,cb>>>(px, ptg, rks, 1, nullptr, thr, 0);
    cgrun(1, ptg);

    // Output
    k_copy<<<EW,256>>>((float*)d_out, px, BCN);
}

// round 3
// speedup vs baseline: 1.5406x; 1.5406x over previous
#include <cuda_runtime.h>

#define BV 2
#define CV 3
#define HV 512
#define WV 512
#define NPIX (HV*WV)
#define CN (CV*NPIX)
#define BCN (BV*CN)
#define GH 64
#define GW 64
#define NBIN 9
#define NGRID (BV*CV*GH*GW*NBIN*2)
#define EPSF 1e-8f
#define CG_TOL 1e-4f
#define NRED 256

// register-blocked conv config: 32x8 threads, 4 rows per thread -> 32x32 tile
#define BX 32
#define BY 8
#define RY 4
#define TB (BX*BY)          // 256 threads
#define TS 32               // output tile side

// ---------------- scratch (device globals; no allocation) ----------------
__device__ float g_x[BCN];
__device__ float g_r[BCN];
__device__ float g_p[BCN];
__device__ float g_t[BCN];
__device__ float g_u[BCN];
__device__ float g_d[BV*6*CN];
__device__ float g_v[BV*5*CN];
__device__ float g_Rp[BV*5*CN];
__device__ float g_tgt[BV*5*CN];
__device__ float g_gridA[NGRID];
__device__ float g_gridB[NGRID];
__device__ float g_partN[BV*NRED];
__device__ float g_partD[BV*NRED];
__device__ float g_partR[BV*NRED];
__device__ float g_alpha[BV];
__device__ float g_beta[BV];
__device__ float g_rn[BV];
__device__ float g_r0[BV];
__device__ int   g_done[BV];
__device__ int   g_pfz[BV];

__device__ __forceinline__ float powx(float a, float e){
    if (e == 0.0f) return 1.0f;
    if (e == 1.0f) return a;
    return powf(a, e);
}
__device__ __forceinline__ float sgnf(float v){
    return (v > 0.f) ? 1.f : ((v < 0.f) ? -1.f : 0.f);
}

// ---------------- elementwise ----------------
__global__ void k_copy(float* __restrict__ dst, const float* __restrict__ src, int n){
    int i = blockIdx.x*blockDim.x + threadIdx.x;
    if (i < n) dst[i] = src[i];
}

__global__ void k_axpy_x(){  // x += alpha*p  (gated on done)
    int i = blockIdx.x*blockDim.x + threadIdx.x;
    if (i >= BCN) return;
    int b = i / CN;
    if (g_done[b]) return;
    g_x[i] = fmaf(g_alpha[b], g_p[i], g_x[i]);
}

__global__ void k_updp(){    // p = r + beta*p  (gated on pfreeze)
    int i = blockIdx.x*blockDim.x + threadIdx.x;
    if (i >= BCN) return;
    int b = i / CN;
    if (g_pfz[b]) return;
    g_p[i] = fmaf(g_beta[b], g_p[i], g_r[i]);
}

// ---------------- 15x15 cross-correlation (optionally minus `sub`) ----------------
__global__ void __launch_bounds__(TB)
k_conv15(const float* __restrict__ src, float* __restrict__ dst,
         const float* __restrict__ kern, const float* __restrict__ sub,
         int gated)
{
    int z = blockIdx.z; int b = z / CV;
    if (gated && g_done[b]) return;
    __shared__ float tile[TS+14][TS+14];
    __shared__ float sk[225];
    const float* sp = src + z*NPIX;
    int x0 = blockIdx.x*TS - 7, y0 = blockIdx.y*TS - 7;
    int tid = threadIdx.y*BX + threadIdx.x;
    for (int i = tid; i < (TS+14)*(TS+14); i += TB){
        int ty = i/(TS+14), tx = i - ty*(TS+14);
        int gy = y0+ty, gx = x0+tx;
        tile[ty][tx] = ((unsigned)gy < HV && (unsigned)gx < WV) ? sp[gy*WV+gx] : 0.f;
    }
    const float* kb = kern + b*225;
    for (int i = tid; i < 225; i += TB) sk[i] = kb[i];
    __syncthreads();
    float acc[RY] = {0.f,0.f,0.f,0.f};
    int rbase = threadIdx.y*RY;
    #pragma unroll
    for (int v = 0; v < 15; v++){
        float win[RY+14];
        #pragma unroll
        for (int j = 0; j < RY+14; j++) win[j] = tile[rbase+j][threadIdx.x+v];
        #pragma unroll
        for (int u = 0; u < 15; u++){
            float kv = sk[u*15+v];
            #pragma unroll
            for (int q = 0; q < RY; q++) acc[q] = fmaf(kv, win[u+q], acc[q]);
        }
    }
    int gx = blockIdx.x*TS + threadIdx.x;
    int gyb = blockIdx.y*TS + rbase;
    #pragma unroll
    for (int q = 0; q < RY; q++){
        int oi = z*NPIX + (gyb+q)*WV + gx;
        float o = acc[q];
        if (sub) o -= sub[oi];
        dst[oi] = o;
    }
}

// ---------------- bank of 6 5x5 (skips filters with dkw==0; consumers skip too) ------
__global__ void __launch_bounds__(TB)
k_bank6(const float* __restrict__ src, float* __restrict__ dst,
        const float* __restrict__ dks, const float* __restrict__ dkw,
        int stage, int gated)
{
    int z = blockIdx.z; int b = z/CV, c = z - b*CV;
    if (gated && g_done[b]) return;
    __shared__ float tile[TS+4][TS+4];
    __shared__ float sk[150];
    __shared__ float swt[6];
    const float* sp = src + z*NPIX;
    int x0 = blockIdx.x*TS - 2, y0 = blockIdx.y*TS - 2;
    int tid = threadIdx.y*BX + threadIdx.x;
    for (int i = tid; i < (TS+4)*(TS+4); i += TB){
        int ty = i/(TS+4), tx = i - ty*(TS+4);
        int gy = y0+ty, gx = x0+tx;
        tile[ty][tx] = ((unsigned)gy < HV && (unsigned)gx < WV) ? sp[gy*WV+gx] : 0.f;
    }
    const float* kb = dks + stage*150;
    for (int i = tid; i < 150; i += TB) sk[i] = kb[i];
    if (tid < 6) swt[tid] = dkw[stage*6 + tid];
    __syncthreads();
    int rbase = threadIdx.y*RY;
    int gx = blockIdx.x*TS + threadIdx.x;
    int gyb = blockIdx.y*TS + rbase;
    for (int n = 0; n < 6; n++){
        if (swt[n] == 0.f) continue;           // exact: zero-weight term contributes 0
        float acc[RY] = {0.f,0.f,0.f,0.f};
        #pragma unroll
        for (int v = 0; v < 5; v++){
            float win[RY+4];
            #pragma unroll
            for (int j = 0; j < RY+4; j++) win[j] = tile[rbase+j][threadIdx.x+v];
            #pragma unroll
            for (int u = 0; u < 5; u++){
                float kv = sk[n*25+u*5+v];
                #pragma unroll
                for (int q = 0; q < RY; q++) acc[q] = fmaf(kv, win[u+q], acc[q]);
            }
        }
        #pragma unroll
        for (int q = 0; q < RY; q++)
            dst[(b*6+n)*CN + c*NPIX + (gyb+q)*WV + gx] = acc[q];
    }
}

// ---------------- adjoint bank6: u = sum_n conv(2*dkw_n*d_n, flip(dk_n)) ----------------
__global__ void __launch_bounds__(TB)
k_bank6T(const float* __restrict__ dsrc, float* __restrict__ dst,
         const float* __restrict__ dks, const float* __restrict__ dkw,
         int stage, int gated)
{
    int z = blockIdx.z; int b = z/CV, c = z - b*CV;
    if (gated && g_done[b]) return;
    __shared__ float tile[6][TS+4][TS+4];
    __shared__ float sk[150];
    __shared__ float swt[6];
    int x0 = blockIdx.x*TS - 2, y0 = blockIdx.y*TS - 2;
    int tid = threadIdx.y*BX + threadIdx.x;
    const float* kb = dks + stage*150;
    for (int i = tid; i < 150; i += TB){ int n = i/25, j = i - n*25; sk[i] = kb[n*25 + 24 - j]; }
    if (tid < 6) swt[tid] = dkw[stage*6 + tid];
    __syncthreads();
    const int TT = (TS+4)*(TS+4);
    for (int n = 0; n < 6; n++){
        if (swt[n] == 0.f) continue;
        float w2 = 2.f*swt[n];
        for (int i = tid; i < TT; i += TB){
            int ty = i/(TS+4), tx = i - ty*(TS+4);
            int gy = y0+ty, gx = x0+tx;
            float v = 0.f;
            if ((unsigned)gy < HV && (unsigned)gx < WV)
                v = w2*dsrc[(b*6+n)*CN + c*NPIX + gy*WV + gx];
            tile[n][ty][tx] = v;
        }
    }
    __syncthreads();
    float acc[RY] = {0.f,0.f,0.f,0.f};
    int rbase = threadIdx.y*RY;
    for (int n = 0; n < 6; n++){
        if (swt[n] == 0.f) continue;
        #pragma unroll
        for (int v = 0; v < 5; v++){
            float win[RY+4];
            #pragma unroll
            for (int j = 0; j < RY+4; j++) win[j] = tile[n][rbase+j][threadIdx.x+v];
            #pragma unroll
            for (int u = 0; u < 5; u++){
                float kv = sk[n*25+u*5+v];
                #pragma unroll
                for (int q = 0; q < RY; q++) acc[q] = fmaf(kv, win[u+q], acc[q]);
            }
        }
    }
    int gx = blockIdx.x*TS + threadIdx.x;
    int gyb = blockIdx.y*TS + rbase;
    #pragma unroll
    for (int q = 0; q < RY; q++)
        dst[z*NPIX + (gyb+q)*WV + gx] = acc[q];
}

// ---------------- bank of 5 5x5: out = conv - tgt  OR  shrink(conv, thr) ----------------
__global__ void __launch_bounds__(TB)
k_bank5(const float* __restrict__ src, float* __restrict__ dst,
        const float* __restrict__ rks, int stage,
        const float* __restrict__ tgt, const float* __restrict__ thr,
        int gated)
{
    int z = blockIdx.z; int b = z/CV, c = z - b*CV;
    if (gated && g_done[b]) return;
    __shared__ float tile[TS+4][TS+4];
    __shared__ float sk[125];
    const float* sp = src + z*NPIX;
    int x0 = blockIdx.x*TS - 2, y0 = blockIdx.y*TS - 2;
    int tid = threadIdx.y*BX + threadIdx.x;
    for (int i = tid; i < (TS+4)*(TS+4); i += TB){
        int ty = i/(TS+4), tx = i - ty*(TS+4);
        int gy = y0+ty, gx = x0+tx;
        tile[ty][tx] = ((unsigned)gy < HV && (unsigned)gx < WV) ? sp[gy*WV+gx] : 0.f;
    }
    const float* kb = rks + stage*125;
    for (int i = tid; i < 125; i += TB) sk[i] = kb[i];
    __syncthreads();
    float acc[5][RY];
    #pragma unroll
    for (int m = 0; m < 5; m++)
        #pragma unroll
        for (int q = 0; q < RY; q++) acc[m][q] = 0.f;
    int rbase = threadIdx.y*RY;
    #pragma unroll
    for (int v = 0; v < 5; v++){
        float win[RY+4];
        #pragma unroll
        for (int j = 0; j < RY+4; j++) win[j] = tile[rbase+j][threadIdx.x+v];
        #pragma unroll
        for (int m = 0; m < 5; m++)
            #pragma unroll
            for (int u = 0; u < 5; u++){
                float kv = sk[m*25+u*5+v];
                #pragma unroll
                for (int q = 0; q < RY; q++) acc[m][q] = fmaf(kv, win[u+q], acc[m][q]);
            }
    }
    int gx = blockIdx.x*TS + threadIdx.x;
    int gyb = blockIdx.y*TS + rbase;
    #pragma unroll
    for (int m = 0; m < 5; m++)
        #pragma unroll
        for (int q = 0; q < RY; q++){
            int oi = (b*5+m)*CN + c*NPIX + (gyb+q)*WV + gx;
            float o = acc[m][q];
            if (thr){
                o = sgnf(o)*fmaxf(fabsf(o)-thr[m], 0.f);
            } else if (tgt){
                o -= tgt[oi];
            }
            dst[oi] = o;
        }
}

// ---------------- gradient finisher: r = -(conv15T(u) + bank5T(w*rpow*phi(v))) ----------------
__global__ void __launch_bounds__(TB)
k_gradfin(const float* __restrict__ usrc, const float* __restrict__ vsrc,
          float* __restrict__ rdst,
          const float* __restrict__ kern, const float* __restrict__ rks,
          const float* __restrict__ rkw, const float* __restrict__ rpow,
          int stage, int gated)
{
    int z = blockIdx.z; int b = z/CV, c = z - b*CV;
    if (gated && g_done[b]) return;
    __shared__ float su[TS+14][TS+14];
    __shared__ float sv[5][TS+4][TS+4];
    __shared__ float sk[225];
    __shared__ float srk[125];
    int tid = threadIdx.y*BX + threadIdx.x;
    const float* kb = kern + b*225;
    for (int i = tid; i < 225; i += TB) sk[i] = kb[224 - i];             // flipped 15x15
    const float* rb = rks + stage*125;
    for (int i = tid; i < 125; i += TB){ int m = i/25, j = i - m*25; srk[i] = rb[m*25 + 24 - j]; }
    int x0 = blockIdx.x*TS, y0 = blockIdx.y*TS;
    const float* up = usrc + z*NPIX;
    for (int i = tid; i < (TS+14)*(TS+14); i += TB){
        int ty = i/(TS+14), tx = i - ty*(TS+14);
        int gy = y0-7+ty, gx = x0-7+tx;
        su[ty][tx] = ((unsigned)gy < HV && (unsigned)gx < WV) ? up[gy*WV+gx] : 0.f;
    }
    const float* wv = rkw + stage*5;
    const float* pw = rpow + stage*5;
    const int TT = (TS+4)*(TS+4);
    for (int i = tid; i < 5*TT; i += TB){
        int m = i/TT, rem = i - m*TT;
        int ty = rem/(TS+4), tx = rem - ty*(TS+4);
        int gy = y0-2+ty, gx = x0-2+tx;
        float val = 0.f;
        if ((unsigned)gy < HV && (unsigned)gx < WV){
            float vvv = vsrc[(b*5+m)*CN + c*NPIX + gy*WV + gx];
            val = wv[m]*pw[m]*sgnf(vvv)*powx(fabsf(vvv)+EPSF, pw[m]-1.f);
        }
        sv[m][ty][tx] = val;
    }
    __syncthreads();
    float acc[RY] = {0.f,0.f,0.f,0.f};
    int rbase = threadIdx.y*RY;
    #pragma unroll
    for (int v = 0; v < 15; v++){
        float win[RY+14];
        #pragma unroll
        for (int j = 0; j < RY+14; j++) win[j] = su[rbase+j][threadIdx.x+v];
        #pragma unroll
        for (int u = 0; u < 15; u++){
            float kv = sk[u*15+v];
            #pragma unroll
            for (int q = 0; q < RY; q++) acc[q] = fmaf(kv, win[u+q], acc[q]);
        }
    }
    #pragma unroll
    for (int m = 0; m < 5; m++){
        #pragma unroll
        for (int v = 0; v < 5; v++){
            float win[RY+4];
            #pragma unroll
            for (int j = 0; j < RY+4; j++) win[j] = sv[m][rbase+j][threadIdx.x+v];
            #pragma unroll
            for (int u = 0; u < 5; u++){
                float kv = srk[m*25+u*5+v];
                #pragma unroll
                for (int q = 0; q < RY; q++) acc[q] = fmaf(kv, win[u+q], acc[q]);
            }
        }
    }
    int gx = blockIdx.x*TS + threadIdx.x;
    int gyb = blockIdx.y*TS + rbase;
    #pragma unroll
    for (int q = 0; q < RY; q++)
        rdst[z*NPIX + (gyb+q)*WV + gx] = -acc[q];
}

// ---------------- deterministic reductions ----------------
__global__ void k_reduce_dot(const float* __restrict__ a, const float* __restrict__ bb,
                             float* __restrict__ part, int gated)
{
    int b = blockIdx.y;
    if (gated && g_done[b]) return;
    const float* ap = a + b*CN;
    const float* bp = bb ? (bb + b*CN) : ap;
    int t = threadIdx.x;
    float s = 0.f;
    for (int i = blockIdx.x*256 + t; i < CN; i += NRED*256) s = fmaf(ap[i], bp[i], s);
    __shared__ float sh[256];
    sh[t] = s; __syncthreads();
    for (int o = 128; o; o >>= 1){ if (t < o) sh[t] += sh[t+o]; __syncthreads(); }
    if (t == 0) part[b*NRED + blockIdx.x] = sh[0];
}

__global__ void k_reduce_den(const float* __restrict__ dsrc, const float* __restrict__ rpsrc,
                             const float* __restrict__ vsrc,
                             const float* __restrict__ dkw, const float* __restrict__ rkw,
                             const float* __restrict__ rpow, int stage)
{
    int b = blockIdx.y;
    if (g_done[b]) return;
    const float* wb = dkw + stage*6;
    const float* rw = rkw + stage*5;
    const float* pw = rpow + stage*5;
    int t = threadIdx.x;
    float s = 0.f;
    for (int i = blockIdx.x*256 + t; i < CN; i += NRED*256){
        #pragma unroll
        for (int n = 0; n < 6; n++){
            if (wb[n] == 0.f) continue;      // exact: 2*0*d^2 == 0 for finite d
            float dv = dsrc[(b*6+n)*CN + i];
            s = fmaf(2.f*wb[n]*dv, dv, s);
        }
        #pragma unroll
        for (int m = 0; m < 5; m++){
            float rv = rpsrc[(b*5+m)*CN + i];
            float vv = vsrc[(b*5+m)*CN + i];
            float w = rw[m]*pw[m]*(pw[m]-1.f)*powx(fabsf(vv)+EPSF, pw[m]-2.f);
            s = fmaf(w*rv, rv, s);
        }
    }
    __shared__ float sh[256];
    sh[t] = s; __syncthreads();
    for (int o = 128; o; o >>= 1){ if (t < o) sh[t] += sh[t+o]; __syncthreads(); }
    if (t == 0) g_partD[b*NRED + blockIdx.x] = sh[0];
}

// ---------------- scalar logic ----------------
__global__ void k_scal_init(){
    int b = blockIdx.x, t = threadIdx.x;
    __shared__ float sh[NRED];
    sh[t] = g_partR[b*NRED + t]; __syncthreads();
    for (int o = 128; o; o >>= 1){ if (t < o) sh[t] += sh[t+o]; __syncthreads(); }
    if (t == 0){ g_rn[b] = sh[0]; g_r0[b] = sh[0]; g_done[b] = 0; g_pfz[b] = 0; }
}

__global__ void k_scal_alpha(){
    int b = blockIdx.x, t = threadIdx.x;
    __shared__ float sn[NRED], sd[NRED];
    sn[t] = g_partN[b*NRED + t];
    sd[t] = g_partD[b*NRED + t];
    __syncthreads();
    for (int o = 128; o; o >>= 1){ if (t < o){ sn[t] += sn[t+o]; sd[t] += sd[t+o]; } __syncthreads(); }
    if (t == 0 && !g_done[b]) g_alpha[b] = sn[0] / (sd[0] + 1e-12f);
}

__global__ void k_scal_beta(){
    int b = blockIdx.x, t = threadIdx.x;
    __shared__ float sh[NRED];
    sh[t] = g_partR[b*NRED + t]; __syncthreads();
    for (int o = 128; o; o >>= 1){ if (t < o) sh[t] += sh[t+o]; __syncthreads(); }
    if (t == 0){
        if (g_done[b]){
            g_pfz[b] = 1;
        } else {
            float nrn = sh[0];
            g_beta[b] = nrn / (g_rn[b] + 1e-20f);
            int conv = (nrn < CG_TOL * g_r0[b]) ? 1 : 0;
            g_rn[b] = nrn;
            g_pfz[b] = conv;
            g_done[b] = conv;
        }
    }
}

// ---------------- bilateral grid ----------------
__global__ void k_splat(const float* __restrict__ x, float* __restrict__ grid){
    int cell = blockIdx.x*blockDim.x + threadIdx.x;
    if (cell >= BV*CV*GH*GW) return;
    int gx = cell & 63;
    int gy = (cell >> 6) & 63;
    int pc = cell >> 12;                 // b*CV + c
    const float* xp = x + pc*NPIX;
    float bv[NBIN], bw[NBIN];
    #pragma unroll
    for (int z = 0; z < NBIN; z++){ bv[z] = 0.f; bw[z] = 0.f; }
    for (int dy = 0; dy < 8; dy++)
        for (int dx = 0; dx < 8; dx++){
            float I = xp[(gy*8+dy)*WV + gx*8+dx];
            float Ic = fminf(fmaxf(I, 0.f), 1.f);
            int zi = (int)rintf(Ic * (float)(NBIN-1));
            zi = max(0, min(NBIN-1, zi));
            bv[zi] += Ic; bw[zi] += 1.f;
        }
    float* gp = grid + (long)cell*NBIN*2;
    #pragma unroll
    for (int z = 0; z < NBIN; z++){ gp[z*2] = bv[z]; gp[z*2+1] = bw[z]; }
}

__global__ void k_convax(const float* __restrict__ in, float* __restrict__ out,
                         const float* __restrict__ f, int taps, int axis)
{
    int e = blockIdx.x*blockDim.x + threadIdx.x;
    if (e >= NGRID) return;
    int r = taps / 2;
    int z = (e >> 1) % NBIN;
    int cellxy = e / (2*NBIN);
    int gx = cellxy & 63;
    int gy = (cellxy >> 6) & 63;
    int coord, extent, stride;
    if (axis == 0){ coord = gy; extent = GH; stride = GW*NBIN*2; }
    else if (axis == 1){ coord = gx; extent = GW; stride = NBIN*2; }
    else { coord = z; extent = NBIN; stride = 2; }
    float s = 0.f;
    for (int t = 0; t < taps; t++){
        int cc = coord + t - r;
        if (cc >= 0 && cc < extent) s = fmaf(f[t], in[e + (cc - coord)*stride], s);
    }
    out[e] = s;
}

__global__ void k_slice(float* __restrict__ x, const float* __restrict__ grid){
    int i = blockIdx.x*blockDim.x + threadIdx.x;
    if (i >= BCN) return;
    int pc = i / NPIX;
    int pix = i - pc*NPIX;
    int y = pix / WV, xx = pix - y*WV;
    float I = x[i];
    float Ic = fminf(fmaxf(I, 0.f), 1.f);
    float yf = (float)y * 0.125f;
    float xf = (float)xx * 0.125f;
    float zf = Ic * (float)(NBIN-1);
    int y0 = max(0, min(GH-1, (int)floorf(yf)));  int y1 = min(y0+1, GH-1);
    float wy = fminf(fmaxf(yf - (float)y0, 0.f), 1.f);
    int x0 = max(0, min(GW-1, (int)floorf(xf)));  int x1 = min(x0+1, GW-1);
    float wx = fminf(fmaxf(xf - (float)x0, 0.f), 1.f);
    int z0 = max(0, min(NBIN-1, (int)floorf(zf))); int z1 = min(z0+1, NBIN-1);
    float wz = fminf(fmaxf(zf - (float)z0, 0.f), 1.f);
    const float* gp = grid + (long)pc*GH*GW*NBIN*2;
    float a0 = 0.f, a1 = 0.f;
    int ys[2]   = {y0, y1};  float wys[2] = {1.f-wy, wy};
    int xs[2]   = {x0, x1};  float wxs[2] = {1.f-wx, wx};
    int zs[2]   = {z0, z1};  float wzs[2] = {1.f-wz, wz};
    for (int a = 0; a < 2; a++)
        for (int bb = 0; bb < 2; bb++)
            for (int cc = 0; cc < 2; cc++){
                float w = wys[a]*wxs[bb]*wzs[cc];
                int idx = (((ys[a]*GW) + xs[bb])*NBIN + zs[cc])*2;
                a0 = fmaf(w, gp[idx], a0);
                a1 = fmaf(w, gp[idx+1], a1);
            }
    x[i] = a0 / (a1 + 1e-8f);
}

// ---------------- host orchestration ----------------
extern "C" void kernel_launch(void* const* d_in, const int* in_sizes, int n_in,
                              void* d_out, int out_size)
{
    const float* blurred = (const float*)d_in[0];
    const float* kern    = (const float*)d_in[1];
    const float* dks     = (const float*)d_in[2];
    const float* dkw     = (const float*)d_in[3];
    const float* rks     = (const float*)d_in[4];
    const float* rkw     = (const float*)d_in[5];
    const float* rpow    = (const float*)d_in[6];
    const float* fs      = (const float*)d_in[7];
    const float* fr      = (const float*)d_in[8];
    const float* thr     = (const float*)d_in[9];
    const int NCG = 5;

    float *px, *pr, *pp, *pt, *pu, *pd, *pv, *pRp, *ptg, *pgA, *pgB, *ppN, *ppR;
    cudaGetSymbolAddress((void**)&px,  g_x);
    cudaGetSymbolAddress((void**)&pr,  g_r);
    cudaGetSymbolAddress((void**)&pp,  g_p);
    cudaGetSymbolAddress((void**)&pt,  g_t);
    cudaGetSymbolAddress((void**)&pu,  g_u);
    cudaGetSymbolAddress((void**)&pd,  g_d);
    cudaGetSymbolAddress((void**)&pv,  g_v);
    cudaGetSymbolAddress((void**)&pRp, g_Rp);
    cudaGetSymbolAddress((void**)&ptg, g_tgt);
    cudaGetSymbolAddress((void**)&pgA, g_gridA);
    cudaGetSymbolAddress((void**)&pgB, g_gridB);
    cudaGetSymbolAddress((void**)&ppN, g_partN);
    cudaGetSymbolAddress((void**)&ppR, g_partR);

    dim3 cb(BX, BY);
    dim3 cg(WV/TS, HV/TS, BV*CV);
    int EW = (BCN + 255)/256;

    k_copy<<<EW,256>>>(px, blurred, BCN);

    auto grad = [&](int stage, const float* tgt, int gated){
        k_conv15<<<cg,cb>>>(px, pt, kern, blurred, gated);                 // t = Kx - b
        k_bank6<<<cg,cb>>>(pt, pd, dks, dkw, stage, gated);                // d = bank6(t) (active filters)
        k_bank6T<<<cg,cb>>>(pd, pu, dks, dkw, stage, gated);               // u = bank6T(2w d)
        k_bank5<<<cg,cb>>>(px, pv, rks, stage, tgt, nullptr, gated);       // v = bank5(x)-tgt
        k_gradfin<<<cg,cb>>>(pu, pv, pr, kern, rks, rkw, rpow, stage, gated);
    };

    auto cgrun = [&](int stage, const float* tgt){
        grad(stage, tgt, 0);
        k_reduce_dot<<<dim3(NRED,BV),256>>>(pr, nullptr, ppR, 0);
        k_scal_init<<<BV,256>>>();
        k_copy<<<EW,256>>>(pp, pr, BCN);
        for (int it = 0; it < NCG; it++){
            k_reduce_dot<<<dim3(NRED,BV),256>>>(pr, pp, ppN, 1);
            k_conv15<<<cg,cb>>>(pp, pt, kern, nullptr, 1);                 // t = Kp
            k_bank6<<<cg,cb>>>(pt, pd, dks, dkw, stage, 1);                // d = dKp
            k_bank5<<<cg,cb>>>(pp, pRp, rks, stage, nullptr, nullptr, 1);  // Rp
            k_reduce_den<<<dim3(NRED,BV),256>>>(pd, pRp, pv, dkw, rkw, rpow, stage);
            k_scal_alpha<<<BV,256>>>();
            k_axpy_x<<<EW,256>>>();
            grad(stage, tgt, 1);
            k_reduce_dot<<<dim3(NRED,BV),256>>>(pr, nullptr, ppR, 1);
            k_scal_beta<<<BV,256>>>();
            k_updp<<<EW,256>>>();
        }
    };

    cgrun(0, nullptr);

    k_splat<<<(BV*CV*GH*GW + 255)/256, 256>>>(px, pgA);
    int NGE = (NGRID + 255)/256;
    k_convax<<<NGE,256>>>(pgA, pgB, fs, 11, 0);
    k_convax<<<NGE,256>>>(pgB, pgA, fs, 11, 1);
    k_convax<<<NGE,256>>>(pgA, pgB, fr, 5, 2);
    k_slice<<<EW,256>>>(px, pgB);

    k_bank5<<<cg,cb>>>(px, ptg, rks, 1, nullptr, thr, 0);
    cgrun(1, ptg);

    k_copy<<<EW,256>>>((float*)d_out, px, BCN);
}

// round 4
// speedup vs baseline: 1.6976x; 1.1019x over previous
#include <cuda_runtime.h>

#define BV 2
#define CV 3
#define HV 512
#define WV 512
#define NPIX (HV*WV)
#define CN (CV*NPIX)
#define BCN (BV*CN)
#define GH 64
#define GW 64
#define NBIN 9
#define NGRID (BV*CV*GH*GW*NBIN*2)
#define EPSF 1e-8f
#define CG_TOL 1e-4f
#define NRED 256

// ---------------- scratch (device globals; no allocation) ----------------
__device__ float g_x[BCN];
__device__ float g_x2[BCN];
__device__ float g_r[BCN];
__device__ float g_p[BCN];
__device__ float g_t[BCN];
__device__ float g_v[BV*5*CN];
__device__ float g_tgt[BV*5*CN];
__device__ float g_gridA[NGRID];
__device__ float g_gridB[NGRID];
__device__ float g_partN[BV*NRED];
__device__ float g_partD[BV*768];
__device__ float g_partR[BV*NRED];
__device__ float g_alpha[BV];
__device__ float g_beta[BV];
__device__ float g_rn[BV];
__device__ float g_r0[BV];
__device__ int   g_done[BV];

// sparse tap lists (built by k_prep; exact: zero taps contribute exactly 0)
__device__ int   g_dknt[2][6];
__device__ int   g_dkdy[2][6][25];
__device__ int   g_dkdx[2][6][25];
__device__ float g_dkv [2][6][25];
__device__ float g_dkw2[2][6];     // 2*weight (0 if inactive)
__device__ int   g_rknt[2][5];
__device__ int   g_rkdy[2][5][25];
__device__ int   g_rkdx[2][5][25];
__device__ float g_rkv [2][5][25];

__device__ __forceinline__ float powx(float a, float e){
    if (e == 0.0f) return 1.0f;
    if (e == 1.0f) return a;
    return powf(a, e);
}
__device__ __forceinline__ float sgnf(float v){
    return (v > 0.f) ? 1.f : ((v < 0.f) ? -1.f : 0.f);
}

// ---------------- prep: build sparse tap lists ----------------
__global__ void k_prep(const float* __restrict__ dks, const float* __restrict__ dkw,
                       const float* __restrict__ rks)
{
    if (threadIdx.x != 0 || blockIdx.x != 0) return;
    for (int s = 0; s < 2; s++){
        for (int n = 0; n < 6; n++){
            g_dkw2[s][n] = 2.f*dkw[s*6+n];
            int cnt = 0;
            for (int j = 0; j < 25; j++){
                float v = dks[(s*6+n)*25 + j];
                if (v != 0.f){
                    g_dkdy[s][n][cnt] = j/5;
                    g_dkdx[s][n][cnt] = j%5;
                    g_dkv [s][n][cnt] = v;
                    cnt++;
                }
            }
            g_dknt[s][n] = cnt;
        }
        for (int m = 0; m < 5; m++){
            int cnt = 0;
            for (int j = 0; j < 25; j++){
                float v = rks[(s*5+m)*25 + j];
                if (v != 0.f){
                    g_rkdy[s][m][cnt] = j/5;
                    g_rkdx[s][m][cnt] = j%5;
                    g_rkv [s][m][cnt] = v;
                    cnt++;
                }
            }
            g_rknt[s][m] = cnt;
        }
    }
}

// ---------------- elementwise copy ----------------
__global__ void k_copy(float* __restrict__ dst, const float* __restrict__ src, int n){
    int i = blockIdx.x*blockDim.x + threadIdx.x;
    if (i < n) dst[i] = src[i];
}

// ---------------- 15x15 conv, optional (x + alpha*p) input & x-out, optional -sub ----
// out tile 32 wide x 64 tall, 256 threads, 8 rows/thread
__global__ void __launch_bounds__(256)
k_conv15(const float* __restrict__ src, float* __restrict__ dst,
         const float* __restrict__ kern, const float* __restrict__ sub,
         const float* __restrict__ pvec, float* __restrict__ xout, int gated)
{
    int z = blockIdx.z; int b = z / CV;
    if (gated && g_done[b]) return;
    __shared__ float tile[78][46];
    __shared__ float sk[225];
    const float* sp = src + z*NPIX;
    const float* pp = pvec ? pvec + z*NPIX : nullptr;
    float al = pvec ? g_alpha[b] : 0.f;    // alpha==0 when done -> exact copy
    int x0 = blockIdx.x*32 - 7, y0 = blockIdx.y*64 - 7;
    int tid = threadIdx.y*32 + threadIdx.x;
    for (int i = tid; i < 78*46; i += 256){
        int ty = i/46, tx = i - ty*46;
        int gy = y0+ty, gx = x0+tx;
        float v = 0.f;
        if ((unsigned)gy < HV && (unsigned)gx < WV){
            int gi = gy*WV+gx;
            v = sp[gi];
            if (pp) v = fmaf(al, pp[gi], v);
        }
        tile[ty][tx] = v;
    }
    const float* kb = kern + b*225;
    for (int i = tid; i < 225; i += 256) sk[i] = kb[i];
    __syncthreads();
    float acc[8] = {0.f,0.f,0.f,0.f,0.f,0.f,0.f,0.f};
    int rbase = threadIdx.y*8;
    #pragma unroll
    for (int v = 0; v < 15; v++){
        float win[22];
        #pragma unroll
        for (int j = 0; j < 22; j++) win[j] = tile[rbase+j][threadIdx.x+v];
        #pragma unroll
        for (int u = 0; u < 15; u++){
            float kv = sk[u*15+v];
            #pragma unroll
            for (int q = 0; q < 8; q++) acc[q] = fmaf(kv, win[u+q], acc[q]);
        }
    }
    int gx = blockIdx.x*32 + threadIdx.x;
    int gyb = blockIdx.y*64 + rbase;
    #pragma unroll
    for (int q = 0; q < 8; q++){
        int oi = z*NPIX + (gyb+q)*WV + gx;
        if (xout) xout[oi] = tile[rbase+q+7][threadIdx.x+7];
        float o = acc[q];
        if (sub) o -= sub[oi];
        dst[oi] = o;
    }
}

// ---------------- fused gradient: r = -(K^T bank6T(2w bank6(Kx-b)) + bank5T(phi)) -----
// also writes v = bank5(x) - tgt for the alpha denominator. out tile 32x32, 256 thr, 4 rows/thr
__global__ void __launch_bounds__(256)
k_gradfull(const float* __restrict__ tsrc, const float* __restrict__ xsrc,
           const float* __restrict__ tgt, float* __restrict__ rdst,
           float* __restrict__ vdst,
           const float* __restrict__ kern,
           const float* __restrict__ rkw, const float* __restrict__ rpow,
           int stage, int gated)
{
    int z = blockIdx.z; int b = z/CV, c = z - b*CV;
    if (gated && g_done[b]) return;
    __shared__ float st[54][54];     // t = Kx-b, halo 11
    __shared__ float sd[50][50];     // 2w * bank6_n(t), halo 9
    __shared__ float su[46][46];     // bank6T accum, halo 7
    __shared__ float sx[40][40];     // x, halo 4
    __shared__ float sph[36][36];    // phi_m, halo 2
    __shared__ float sk[225];        // flipped 15x15
    __shared__ float tv[25]; __shared__ int tdy[25], tdx[25];
    int tid = threadIdx.y*32 + threadIdx.x;
    int X0 = blockIdx.x*32, Y0 = blockIdx.y*32;
    const float* tp = tsrc + z*NPIX;
    const float* xp = xsrc + z*NPIX;
    for (int i = tid; i < 54*54; i += 256){
        int ty = i/54, tx = i - ty*54;
        int gy = Y0-11+ty, gx = X0-11+tx;
        st[ty][tx] = ((unsigned)gy < HV && (unsigned)gx < WV) ? tp[gy*WV+gx] : 0.f;
    }
    for (int i = tid; i < 40*40; i += 256){
        int ty = i/40, tx = i - ty*40;
        int gy = Y0-4+ty, gx = X0-4+tx;
        sx[ty][tx] = ((unsigned)gy < HV && (unsigned)gx < WV) ? xp[gy*WV+gx] : 0.f;
    }
    const float* kb = kern + b*225;
    for (int i = tid; i < 225; i += 256) sk[i] = kb[224 - i];
    for (int i = tid; i < 46*46; i += 256) su[i/46][i%46] = 0.f;
    __syncthreads();

    // ---- data term: su += bank6T_n(2w * bank6_n(st)) ----
    for (int n = 0; n < 6; n++){
        float w2 = g_dkw2[stage][n];
        if (w2 == 0.f) continue;
        int nt = g_dknt[stage][n];
        if (tid < nt){ tv[tid] = g_dkv[stage][n][tid]; tdy[tid] = g_dkdy[stage][n][tid]; tdx[tid] = g_dkdx[stage][n][tid]; }
        __syncthreads();
        for (int i = tid; i < 50*50; i += 256){
            int ty = i/50, tx = i - ty*50;
            float a = 0.f;
            for (int t = 0; t < nt; t++)
                a = fmaf(tv[t], st[ty+tdy[t]][tx+tdx[t]], a);
            sd[ty][tx] = w2*a;
        }
        __syncthreads();
        for (int i = tid; i < 46*46; i += 256){
            int ty = i/46, tx = i - ty*46;
            float a = su[ty][tx];
            for (int t = 0; t < nt; t++)
                a = fmaf(tv[t], sd[ty+4-tdy[t]][tx+4-tdx[t]], a);
            su[ty][tx] = a;
        }
        __syncthreads();
    }

    // ---- K^T on su ----
    float acc[4] = {0.f,0.f,0.f,0.f};
    int rbase = threadIdx.y*4;
    #pragma unroll
    for (int v = 0; v < 15; v++){
        float win[18];
        #pragma unroll
        for (int j = 0; j < 18; j++) win[j] = su[rbase+j][threadIdx.x+v];
        #pragma unroll
        for (int u = 0; u < 15; u++){
            float kv = sk[u*15+v];
            #pragma unroll
            for (int q = 0; q < 4; q++) acc[q] = fmaf(kv, win[u+q], acc[q]);
        }
    }

    // ---- reg term: acc += bank5T_m(rkw*rpow*phi(bank5_m(x) - tgt)); also write v ----
    for (int m = 0; m < 5; m++){
        float wm = rkw[stage*5+m];
        float pm = rpow[stage*5+m];
        int nt = g_rknt[stage][m];
        if (tid < nt){ tv[tid] = g_rkv[stage][m][tid]; tdy[tid] = g_rkdy[stage][m][tid]; tdx[tid] = g_rkdx[stage][m][tid]; }
        __syncthreads();
        for (int i = tid; i < 36*36; i += 256){
            int ty = i/36, tx = i - ty*36;
            int gy = Y0-2+ty, gx = X0-2+tx;
            float ph = 0.f;
            if ((unsigned)gy < HV && (unsigned)gx < WV){
                float vv = 0.f;
                for (int t = 0; t < nt; t++)
                    vv = fmaf(tv[t], sx[ty+tdy[t]][tx+tdx[t]], vv);
                int gi = (b*5+m)*CN + c*NPIX + gy*WV+gx;
                if (tgt) vv -= tgt[gi];
                ph = wm*pm*sgnf(vv)*powx(fabsf(vv)+EPSF, pm-1.f);
                if (ty >= 2 && ty < 34 && tx >= 2 && tx < 34)
                    vdst[gi] = vv;
            }
            sph[ty][tx] = ph;
        }
        __syncthreads();
        for (int q = 0; q < 4; q++){
            int i = rbase + q;
            float a = acc[q];
            for (int t = 0; t < nt; t++)
                a = fmaf(tv[t], sph[i+4-tdy[t]][threadIdx.x+4-tdx[t]], a);
            acc[q] = a;
        }
        __syncthreads();
    }

    int gx = X0 + threadIdx.x;
    #pragma unroll
    for (int q = 0; q < 4; q++)
        rdst[z*NPIX + (Y0+rbase+q)*WV + gx] = -acc[q];
}

// ---------------- fused alpha denominator (tile partial reduction) ----------------
// t = Kp in global; computes sum 2w*(dk_n*t)^2 + sum wGN(v)*(rk_m*p)^2
__global__ void __launch_bounds__(256)
k_den(const float* __restrict__ tsrc, const float* __restrict__ pvec,
      const float* __restrict__ vsrc,
      const float* __restrict__ rkw, const float* __restrict__ rpow,
      int stage)
{
    int z = blockIdx.z; int b = z/CV, c = z - b*CV;
    if (g_done[b]) return;
    __shared__ float stp[36][36];
    __shared__ float spp[36][36];
    int tid = threadIdx.y*32 + threadIdx.x;
    int X0 = blockIdx.x*32, Y0 = blockIdx.y*32;
    const float* tp = tsrc + z*NPIX;
    const float* pp = pvec + z*NPIX;
    for (int i = tid; i < 36*36; i += 256){
        int ty = i/36, tx = i - ty*36;
        int gy = Y0-2+ty, gx = X0-2+tx;
        bool in = ((unsigned)gy < HV && (unsigned)gx < WV);
        stp[ty][tx] = in ? tp[gy*WV+gx] : 0.f;
        spp[ty][tx] = in ? pp[gy*WV+gx] : 0.f;
    }
    __syncthreads();
    float s = 0.f;
    int rbase = threadIdx.y*4;
    for (int q = 0; q < 4; q++){
        int i = rbase + q;
        int gy = Y0 + i, gx = X0 + threadIdx.x;
        for (int n = 0; n < 6; n++){
            float w2 = g_dkw2[stage][n];
            if (w2 == 0.f) continue;
            int nt = g_dknt[stage][n];
            float d = 0.f;
            for (int t = 0; t < nt; t++)
                d = fmaf(g_dkv[stage][n][t], stp[i+g_dkdy[stage][n][t]][threadIdx.x+g_dkdx[stage][n][t]], d);
            s = fmaf(w2*d, d, s);
        }
        for (int m = 0; m < 5; m++){
            int nt = g_rknt[stage][m];
            float rv = 0.f;
            for (int t = 0; t < nt; t++)
                rv = fmaf(g_rkv[stage][m][t], spp[i+g_rkdy[stage][m][t]][threadIdx.x+g_rkdx[stage][m][t]], rv);
            float vv = vsrc[(b*5+m)*CN + c*NPIX + gy*WV+gx];
            float pmv = rpow[stage*5+m];
            float w = rkw[stage*5+m]*pmv*(pmv-1.f)*powx(fabsf(vv)+EPSF, pmv-2.f);
            s = fmaf(w*rv, rv, s);
        }
    }
    __shared__ float sh[256];
    sh[tid] = s; __syncthreads();
    for (int o = 128; o; o >>= 1){ if (tid < o) sh[tid] += sh[tid+o]; __syncthreads(); }
    if (tid == 0)
        g_partD[b*768 + c*256 + blockIdx.y*16 + blockIdx.x] = sh[0];
}

// ---------------- fused p-update + alpha numerator: p = first? r : r + beta*p; num=sum r*p ---
__global__ void k_dotp(int first){
    int b = blockIdx.y;
    if (g_done[b]) return;
    float be = g_beta[b];
    int t = threadIdx.x;
    float s = 0.f;
    for (int i = blockIdx.x*256 + t; i < CN; i += NRED*256){
        int gi = b*CN + i;
        float rv = g_r[gi];
        float pn = first ? rv : fmaf(be, g_p[gi], rv);
        g_p[gi] = pn;
        s = fmaf(rv, pn, s);
    }
    __shared__ float sh[256];
    sh[t] = s; __syncthreads();
    for (int o = 128; o; o >>= 1){ if (t < o) sh[t] += sh[t+o]; __syncthreads(); }
    if (t == 0) g_partN[b*NRED + blockIdx.x] = sh[0];
}

// ---------------- r norm reduction ----------------
__global__ void k_rdot(int gated){
    int b = blockIdx.y;
    if (gated && g_done[b]) return;
    int t = threadIdx.x;
    float s = 0.f;
    for (int i = blockIdx.x*256 + t; i < CN; i += NRED*256){
        float rv = g_r[b*CN + i];
        s = fmaf(rv, rv, s);
    }
    __shared__ float sh[256];
    sh[t] = s; __syncthreads();
    for (int o = 128; o; o >>= 1){ if (t < o) sh[t] += sh[t+o]; __syncthreads(); }
    if (t == 0) g_partR[b*NRED + blockIdx.x] = sh[0];
}

// ---------------- scalar logic ----------------
__global__ void k_scal_init(){
    int b = blockIdx.x, t = threadIdx.x;
    __shared__ float sh[NRED];
    sh[t] = g_partR[b*NRED + t]; __syncthreads();
    for (int o = 128; o; o >>= 1){ if (t < o) sh[t] += sh[t+o]; __syncthreads(); }
    if (t == 0){ g_rn[b] = sh[0]; g_r0[b] = sh[0]; g_done[b] = 0; }
}

__global__ void k_scal_alpha(){
    int b = blockIdx.x, t = threadIdx.x;
    __shared__ float sn[NRED], sd[NRED];
    sn[t] = g_partN[b*NRED + t];
    sd[t] = g_partD[b*768 + t] + g_partD[b*768 + t + 256] + g_partD[b*768 + t + 512];
    __syncthreads();
    for (int o = 128; o; o >>= 1){ if (t < o){ sn[t] += sn[t+o]; sd[t] += sd[t+o]; } __syncthreads(); }
    if (t == 0) g_alpha[b] = g_done[b] ? 0.f : sn[0] / (sd[0] + 1e-12f);
}

__global__ void k_scal_beta(){
    int b = blockIdx.x, t = threadIdx.x;
    __shared__ float sh[NRED];
    sh[t] = g_partR[b*NRED + t]; __syncthreads();
    for (int o = 128; o; o >>= 1){ if (t < o) sh[t] += sh[t+o]; __syncthreads(); }
    if (t == 0 && !g_done[b]){
        float nrn = sh[0];
        g_beta[b] = nrn / (g_rn[b] + 1e-20f);
        int conv = (nrn < CG_TOL * g_r0[b]) ? 1 : 0;
        g_rn[b] = nrn;
        g_done[b] = conv;
    }
}

// ---------------- prior targets: tgt = shrink(bank5(x), thr) ----------------
__global__ void __launch_bounds__(256)
k_prior(const float* __restrict__ xsrc, float* __restrict__ dst,
        const float* __restrict__ thr, int stage)
{
    int z = blockIdx.z; int b = z/CV, c = z - b*CV;
    __shared__ float sxx[36][36];
    int tid = threadIdx.y*32 + threadIdx.x;
    int X0 = blockIdx.x*32, Y0 = blockIdx.y*32;
    const float* xp = xsrc + z*NPIX;
    for (int i = tid; i < 36*36; i += 256){
        int ty = i/36, tx = i - ty*36;
        int gy = Y0-2+ty, gx = X0-2+tx;
        sxx[ty][tx] = ((unsigned)gy < HV && (unsigned)gx < WV) ? xp[gy*WV+gx] : 0.f;
    }
    __syncthreads();
    int rbase = threadIdx.y*4;
    int gx = X0 + threadIdx.x;
    for (int m = 0; m < 5; m++){
        int nt = g_rknt[stage][m];
        float th = thr[m];
        for (int q = 0; q < 4; q++){
            int i = rbase + q;
            float v = 0.f;
            for (int t = 0; t < nt; t++)
                v = fmaf(g_rkv[stage][m][t], sxx[i+g_rkdy[stage][m][t]][threadIdx.x+g_rkdx[stage][m][t]], v);
            dst[(b*5+m)*CN + c*NPIX + (Y0+i)*WV + gx] = sgnf(v)*fmaxf(fabsf(v)-th, 0.f);
        }
    }
}

// ---------------- bilateral grid ----------------
__global__ void k_splat(const float* __restrict__ x, float* __restrict__ grid){
    int cell = blockIdx.x*blockDim.x + threadIdx.x;
    if (cell >= BV*CV*GH*GW) return;
    int gx = cell & 63;
    int gy = (cell >> 6) & 63;
    int pc = cell >> 12;
    const float* xp = x + pc*NPIX;
    float bv[NBIN], bw[NBIN];
    #pragma unroll
    for (int z = 0; z < NBIN; z++){ bv[z] = 0.f; bw[z] = 0.f; }
    for (int dy = 0; dy < 8; dy++)
        for (int dx = 0; dx < 8; dx++){
            float I = xp[(gy*8+dy)*WV + gx*8+dx];
            float Ic = fminf(fmaxf(I, 0.f), 1.f);
            int zi = (int)rintf(Ic * (float)(NBIN-1));
            zi = max(0, min(NBIN-1, zi));
            bv[zi] += Ic; bw[zi] += 1.f;
        }
    float* gp = grid + (long)cell*NBIN*2;
    #pragma unroll
    for (int z = 0; z < NBIN; z++){ gp[z*2] = bv[z]; gp[z*2+1] = bw[z]; }
}

__global__ void k_convax(const float* __restrict__ in, float* __restrict__ out,
                         const float* __restrict__ f, int taps, int axis)
{
    int e = blockIdx.x*blockDim.x + threadIdx.x;
    if (e >= NGRID) return;
    int r = taps / 2;
    int z = (e >> 1) % NBIN;
    int cellxy = e / (2*NBIN);
    int gx = cellxy & 63;
    int gy = (cellxy >> 6) & 63;
    int coord, extent, stride;
    if (axis == 0){ coord = gy; extent = GH; stride = GW*NBIN*2; }
    else if (axis == 1){ coord = gx; extent = GW; stride = NBIN*2; }
    else { coord = z; extent = NBIN; stride = 2; }
    float s = 0.f;
    for (int t = 0; t < taps; t++){
        int cc = coord + t - r;
        if (cc >= 0 && cc < extent) s = fmaf(f[t], in[e + (cc - coord)*stride], s);
    }
    out[e] = s;
}

__global__ void k_slice(float* __restrict__ x, const float* __restrict__ grid){
    int i = blockIdx.x*blockDim.x + threadIdx.x;
    if (i >= BCN) return;
    int pc = i / NPIX;
    int pix = i - pc*NPIX;
    int y = pix / WV, xx = pix - y*WV;
    float I = x[i];
    float Ic = fminf(fmaxf(I, 0.f), 1.f);
    float yf = (float)y * 0.125f;
    float xf = (float)xx * 0.125f;
    float zf = Ic * (float)(NBIN-1);
    int y0 = max(0, min(GH-1, (int)floorf(yf)));  int y1 = min(y0+1, GH-1);
    float wy = fminf(fmaxf(yf - (float)y0, 0.f), 1.f);
    int x0 = max(0, min(GW-1, (int)floorf(xf)));  int x1 = min(x0+1, GW-1);
    float wx = fminf(fmaxf(xf - (float)x0, 0.f), 1.f);
    int z0 = max(0, min(NBIN-1, (int)floorf(zf))); int z1 = min(z0+1, NBIN-1);
    float wz = fminf(fmaxf(zf - (float)z0, 0.f), 1.f);
    const float* gp = grid + (long)pc*GH*GW*NBIN*2;
    float a0 = 0.f, a1 = 0.f;
    int ys[2]   = {y0, y1};  float wys[2] = {1.f-wy, wy};
    int xs[2]   = {x0, x1};  float wxs[2] = {1.f-wx, wx};
    int zs[2]   = {z0, z1};  float wzs[2] = {1.f-wz, wz};
    for (int a = 0; a < 2; a++)
        for (int bb = 0; bb < 2; bb++)
            for (int cc = 0; cc < 2; cc++){
                float w = wys[a]*wxs[bb]*wzs[cc];
                int idx = (((ys[a]*GW) + xs[bb])*NBIN + zs[cc])*2;
                a0 = fmaf(w, gp[idx], a0);
                a1 = fmaf(w, gp[idx+1], a1);
            }
    x[i] = a0 / (a1 + 1e-8f);
}

// ---------------- host orchestration ----------------
extern "C" void kernel_launch(void* const* d_in, const int* in_sizes, int n_in,
                              void* d_out, int out_size)
{
    const float* blurred = (const float*)d_in[0];
    const float* kern    = (const float*)d_in[1];
    const float* dks     = (const float*)d_in[2];
    const float* dkw     = (const float*)d_in[3];
    const float* rks     = (const float*)d_in[4];
    const float* rkw     = (const float*)d_in[5];
    const float* rpow    = (const float*)d_in[6];
    const float* fs      = (const float*)d_in[7];
    const float* fr      = (const float*)d_in[8];
    const float* thr     = (const float*)d_in[9];
    const int NCG = 5;

    float *px, *px2, *pr, *pp, *pt, *pv, *ptg, *pgA, *pgB;
    cudaGetSymbolAddress((void**)&px,  g_x);
    cudaGetSymbolAddress((void**)&px2, g_x2);
    cudaGetSymbolAddress((void**)&pr,  g_r);
    cudaGetSymbolAddress((void**)&pp,  g_p);
    cudaGetSymbolAddress((void**)&pt,  g_t);
    cudaGetSymbolAddress((void**)&pv,  g_v);
    cudaGetSymbolAddress((void**)&ptg, g_tgt);
    cudaGetSymbolAddress((void**)&pgA, g_gridA);
    cudaGetSymbolAddress((void**)&pgB, g_gridB);

    dim3 cb8(32, 8);
    dim3 cg15(WV/32, HV/64, BV*CV);   // conv15: 32x64 tiles
    dim3 cg32(WV/32, HV/32, BV*CV);   // 32x32 tiles
    int EW = (BCN + 255)/256;

    k_prep<<<1,32>>>(dks, dkw, rks);
    k_copy<<<EW,256>>>(px, blurred, BCN);

    // runs one CG solve; returns which buffer holds the final x
    auto cgrun = [&](int stage, const float* tgt, float* xinit) -> float* {
        // initial gradient
        k_conv15<<<cg15,cb8>>>(xinit, pt, kern, blurred, nullptr, nullptr, 0);
        k_gradfull<<<cg32,cb8>>>(pt, xinit, tgt, pr, pv, kern, rkw, rpow, stage, 0);
        k_rdot<<<dim3(NRED,BV),256>>>(0);
        k_scal_init<<<BV,256>>>();
        float* xcur = xinit;
        for (int it = 0; it < NCG; it++){
            float* xnext = (xcur == px) ? px2 : px;
            k_dotp<<<dim3(NRED,BV),256>>>(it == 0);                       // p update + num
            k_conv15<<<cg15,cb8>>>(pp, pt, kern, nullptr, nullptr, nullptr, 1);  // t = Kp
            k_den<<<cg32,cb8>>>(pt, pp, pv, rkw, rpow, stage);            // den partials
            k_scal_alpha<<<BV,256>>>();
            // x_new = x + alpha*p (ping-pong); t = K x_new - b
            k_conv15<<<cg15,cb8>>>(xcur, pt, kern, blurred, pp, xnext, 0);
            k_gradfull<<<cg32,cb8>>>(pt, xnext, tgt, pr, pv, kern, rkw, rpow, stage, 1);
            k_rdot<<<dim3(NRED,BV),256>>>(1);
            k_scal_beta<<<BV,256>>>();
            xcur = xnext;
        }
        return xcur;
    };

    // Stage 0 CG (targets = 0) starting from g_x
    float* xs0 = cgrun(0, nullptr, px);   // ends in g_x2 (5 iters from g_x)

    // Bilateral grid filter (in place on xs0)
    k_splat<<<(BV*CV*GH*GW + 255)/256, 256>>>(xs0, pgA);
    int NGE = (NGRID + 255)/256;
    k_convax<<<NGE,256>>>(pgA, pgB, fs, 11, 0);
    k_convax<<<NGE,256>>>(pgB, pgA, fs, 11, 1);
    k_convax<<<NGE,256>>>(pgA, pgB, fr, 5, 2);
    k_slice<<<EW,256>>>(xs0, pgB);

    // Prior targets (rk stage 1, thresholds stage 0), then stage-1 CG
    k_prior<<<cg32,cb8>>>(xs0, ptg, thr, 1);
    float* xs1 = cgrun(1, ptg, xs0);

    k_copy<<<EW,256>>>((float*)d_out, xs1, BCN);
}

// round 5
// speedup vs baseline: 2.1492x; 1.2661x over previous
#include <cuda_runtime.h>

#define BV 2
#define CV 3
#define HV 512
#define WV 512
#define NPIX (HV*WV)
#define CN (CV*NPIX)
#define BCN (BV*CN)
#define GH 64
#define GW 64
#define NBIN 9
#define NGRID (BV*CV*GH*GW*NBIN*2)
#define EPSF 1e-8f
#define CG_TOL 1e-4f

// ---------------- scratch (device globals; no allocation) ----------------
__device__ float g_x[BCN];
__device__ float g_x2[BCN];
__device__ float g_r[BCN];
__device__ float g_p[BCN];
__device__ float g_t[BCN];    // tx ping
__device__ float g_t2[BCN];   // tx pong
__device__ float g_tp[BCN];   // Kp
__device__ float g_v[BV*5*CN];
__device__ float g_tgt[BV*5*CN];
__device__ float g_gridA[NGRID];
__device__ float g_gridB[NGRID];
__device__ float g_partN[BV*256];
__device__ float g_partD[BV*768];
__device__ float g_partR[BV*768];
__device__ float g_r0[BV];
__device__ float g_rnS[2][BV];
__device__ int   g_doneS[2][BV];

// sparse tap metadata (exact: zero taps contribute exactly 0 via fmaf)
__device__ int   g_dknt[2][6];
__device__ int   g_dkdy[2][6][25];
__device__ int   g_dkdx[2][6][25];
__device__ float g_dkv [2][6][25];
__device__ float g_dkw2[2][6];
__device__ int   g_rknt[2][5];
__device__ int   g_rkdy[2][5][25];
__device__ int   g_rkdx[2][5][25];
__device__ float g_rkv [2][5][25];

__device__ __forceinline__ float powx(float a, float e){
    if (e == 0.0f) return 1.0f;
    if (e == 1.0f) return a;
    return powf(a, e);
}
__device__ __forceinline__ float sgnf(float v){
    return (v > 0.f) ? 1.f : ((v < 0.f) ? -1.f : 0.f);
}

// ---------------- prep ----------------
__global__ void k_prep(const float* __restrict__ dks, const float* __restrict__ dkw,
                       const float* __restrict__ rks)
{
    if (threadIdx.x != 0 || blockIdx.x != 0) return;
    for (int s = 0; s < 2; s++){
        for (int n = 0; n < 6; n++){
            g_dkw2[s][n] = 2.f*dkw[s*6+n];
            int cnt = 0;
            for (int j = 0; j < 25; j++){
                float v = dks[(s*6+n)*25 + j];
                if (v != 0.f){
                    g_dkdy[s][n][cnt] = j/5; g_dkdx[s][n][cnt] = j%5;
                    g_dkv [s][n][cnt] = v; cnt++;
                }
            }
            g_dknt[s][n] = cnt;
        }
        for (int m = 0; m < 5; m++){
            int cnt = 0;
            for (int j = 0; j < 25; j++){
                float v = rks[(s*5+m)*25 + j];
                if (v != 0.f){
                    g_rkdy[s][m][cnt] = j/5; g_rkdx[s][m][cnt] = j%5;
                    g_rkv [s][m][cnt] = v; cnt++;
                }
            }
            g_rknt[s][m] = cnt;
        }
    }
}

__global__ void k_copy(float* __restrict__ dst, const float* __restrict__ src, int n){
    int i = blockIdx.x*blockDim.x + threadIdx.x;
    if (i < n) dst[i] = src[i];
}

// ---------------- 15x15 cross-correlation (opt minus sub), 32x64 tile ----------------
__global__ void __launch_bounds__(256)
k_conv15(const float* __restrict__ src, float* __restrict__ dst,
         const float* __restrict__ kern, const float* __restrict__ sub,
         int gated, int slot)
{
    int z = blockIdx.z; int b = z / CV;
    if (gated && g_doneS[slot][b]) return;
    __shared__ float tile[78][46];
    __shared__ float sk[225];
    const float* sp = src + z*NPIX;
    int x0 = blockIdx.x*32 - 7, y0 = blockIdx.y*64 - 7;
    int tx_ = threadIdx.x, ty_ = threadIdx.y;
    int tid = ty_*32 + tx_;
    for (int row = ty_; row < 78; row += 8){
        int gy = y0 + row;
        bool iny = (unsigned)gy < HV;
        for (int col = tx_; col < 46; col += 32){
            int gx = x0 + col;
            tile[row][col] = (iny && (unsigned)gx < WV) ? sp[gy*WV+gx] : 0.f;
        }
    }
    const float* kb = kern + b*225;
    for (int i = tid; i < 225; i += 256) sk[i] = kb[i];
    __syncthreads();
    float acc[8] = {0.f,0.f,0.f,0.f,0.f,0.f,0.f,0.f};
    int rbase = ty_*8;
    for (int v = 0; v < 15; v++){
        float win[22];
        #pragma unroll
        for (int j = 0; j < 22; j++) win[j] = tile[rbase+j][tx_+v];
        #pragma unroll
        for (int u = 0; u < 15; u++){
            float kv = sk[u*15+v];
            #pragma unroll
            for (int q = 0; q < 8; q++) acc[q] = fmaf(kv, win[u+q], acc[q]);
        }
    }
    int gx = blockIdx.x*32 + tx_;
    int gyb = blockIdx.y*64 + rbase;
    #pragma unroll
    for (int q = 0; q < 8; q++){
        int oi = z*NPIX + (gyb+q)*WV + gx;
        float o = acc[q];
        if (sub) o -= sub[oi];
        dst[oi] = o;
    }
}

// ---------------- p update + num partial + beta/done scalar logic ----------------
__global__ void k_dotp(int first, int slot){
    int b = blockIdx.y, t = threadIdx.x;
    __shared__ float sh[256];
    __shared__ float s_beta;
    __shared__ int s_freeze;
    float a = g_partR[b*768+t] + g_partR[b*768+256+t] + g_partR[b*768+512+t];
    sh[t] = a; __syncthreads();
    for (int o = 128; o; o >>= 1){ if (t < o) sh[t] += sh[t+o]; __syncthreads(); }
    if (t == 0){
        float nrn = sh[0];
        int done_prev = first ? 0 : g_doneS[slot][b];
        float rn_prev = first ? 1.f : g_rnS[slot][b];
        float r0 = first ? nrn : g_r0[b];
        float beta = nrn/(rn_prev + 1e-20f);
        int conv_now = (!first) && (nrn < CG_TOL*r0);
        s_beta = first ? 0.f : beta;
        s_freeze = first ? 0 : (done_prev | conv_now);
        if (blockIdx.x == 0){
            g_doneS[slot^1][b] = done_prev | conv_now;
            g_rnS[slot^1][b] = done_prev ? rn_prev : nrn;
            if (first) g_r0[b] = nrn;
        }
    }
    __syncthreads();
    float beta = s_beta;
    int freeze = s_freeze;
    float s = 0.f;
    if (first){
        for (int i = blockIdx.x*256 + t; i < CN; i += 65536){
            int gi = b*CN + i;
            float rv = g_r[gi];
            g_p[gi] = rv;
            s = fmaf(rv, rv, s);
        }
    } else if (!freeze){
        for (int i = blockIdx.x*256 + t; i < CN; i += 65536){
            int gi = b*CN + i;
            float rv = g_r[gi];
            float pn = fmaf(beta, g_p[gi], rv);
            g_p[gi] = pn;
            s = fmaf(rv, pn, s);
        }
    } else {
        for (int i = blockIdx.x*256 + t; i < CN; i += 65536)
            s = fmaf(g_r[b*CN+i], g_p[b*CN+i], s);
    }
    __syncthreads();
    sh[t] = s; __syncthreads();
    for (int o = 128; o; o >>= 1){ if (t < o) sh[t] += sh[t+o]; __syncthreads(); }
    if (t == 0) g_partN[b*256 + blockIdx.x] = sh[0];
}

// ---------------- alpha denominator partials ----------------
__global__ void __launch_bounds__(256)
k_den(const float* __restrict__ tsrc, const float* __restrict__ pvec,
      const float* __restrict__ vsrc,
      const float* __restrict__ rkw, const float* __restrict__ rpow,
      int stage, int slot)
{
    int z = blockIdx.z; int b = z/CV, c = z - b*CV;
    if (g_doneS[slot][b]) return;
    __shared__ float stp[36*36], spp[36*36];
    __shared__ float dV[150]; __shared__ int dO[150];
    __shared__ float rV[125]; __shared__ int rO[125];
    __shared__ float sh[256];
    int tx_ = threadIdx.x, ty_ = threadIdx.y;
    int tid = ty_*32 + tx_;
    int X0 = blockIdx.x*32, Y0 = blockIdx.y*32;
    const float* tp = tsrc + z*NPIX;
    const float* pp = pvec + z*NPIX;
    for (int row = ty_; row < 36; row += 8){
        int gy = Y0-2+row;
        bool iny = (unsigned)gy < HV;
        for (int col = tx_; col < 36; col += 32){
            int gx = X0-2+col;
            bool in = iny && (unsigned)gx < WV;
            stp[row*36+col] = in ? tp[gy*WV+gx] : 0.f;
            spp[row*36+col] = in ? pp[gy*WV+gx] : 0.f;
        }
    }
    for (int i = tid; i < 150; i += 256){
        int n = i/25, j = i - n*25;
        dV[i] = g_dkv[stage][n][j];
        dO[i] = g_dkdy[stage][n][j]*36 + g_dkdx[stage][n][j];
    }
    for (int i = tid; i < 125; i += 256){
        int m = i/25, j = i - m*25;
        rV[i] = g_rkv[stage][m][j];
        rO[i] = g_rkdy[stage][m][j]*36 + g_rkdx[stage][m][j];
    }
    __syncthreads();
    float s = 0.f;
    int rbase = ty_*4;
    for (int q = 0; q < 4; q++){
        int i = rbase + q;
        int base = i*36 + tx_;
        for (int n = 0; n < 6; n++){
            float w2 = g_dkw2[stage][n];
            if (w2 == 0.f) continue;
            int nt = g_dknt[stage][n];
            float d = 0.f;
            for (int t = 0; t < nt; t++) d = fmaf(dV[n*25+t], stp[base+dO[n*25+t]], d);
            s = fmaf(w2*d, d, s);
        }
        int gi0 = c*NPIX + (Y0+i)*WV + X0 + tx_;
        for (int m = 0; m < 5; m++){
            int nt = g_rknt[stage][m];
            float rv = 0.f;
            for (int t = 0; t < nt; t++) rv = fmaf(rV[m*25+t], spp[base+rO[m*25+t]], rv);
            float vv = vsrc[(b*5+m)*CN + gi0];
            float pmv = rpow[stage*5+m];
            float w = rkw[stage*5+m]*pmv*(pmv-1.f)*powx(fabsf(vv)+EPSF, pmv-2.f);
            s = fmaf(w*rv, rv, s);
        }
    }
    sh[tid] = s; __syncthreads();
    for (int o = 128; o; o >>= 1){ if (tid < o) sh[tid] += sh[tid+o]; __syncthreads(); }
    if (tid == 0) g_partD[b*768 + c*256 + blockIdx.y*16 + blockIdx.x] = sh[0];
}

// ---------------- fused gradient + x/t update + r-norm partial ----------------
__global__ void __launch_bounds__(256,4)
k_gradfull(const float* __restrict__ xsrc, const float* __restrict__ psrc,
           const float* __restrict__ tsrc, const float* __restrict__ tpsrc,
           float* __restrict__ xdst, float* __restrict__ tdst,
           const float* __restrict__ tgt, float* __restrict__ rdst,
           float* __restrict__ vdst,
           const float* __restrict__ kern,
           const float* __restrict__ rkw, const float* __restrict__ rpow,
           int stage, int slot, int first)
{
    int z = blockIdx.z; int b = z/CV, c = z - b*CV;
    int tx_ = threadIdx.x, ty_ = threadIdx.y;
    int tid = ty_*32 + tx_;
    int X0 = blockIdx.x*32, Y0 = blockIdx.y*32;

    __shared__ float st[54][54];
    __shared__ float su[46][46];
    __shared__ float sbuf[2500];
    __shared__ float sx[40][40];
    __shared__ float sk[225];
    __shared__ float sh[256];
    __shared__ float sh2[256];
    __shared__ float s_alpha;
    __shared__ float tv[25]; __shared__ int oA[25], oB[25];

    // alpha (deterministic, redundant per block)
    if (first){
        if (tid == 0) s_alpha = 0.f;
    } else {
        float sn = g_partN[b*256 + tid];
        float sd = g_partD[b*768 + tid] + g_partD[b*768 + 256 + tid] + g_partD[b*768 + 512 + tid];
        sh[tid] = sn; sh2[tid] = sd; __syncthreads();
        for (int o = 128; o; o >>= 1){
            if (tid < o){ sh[tid] += sh[tid+o]; sh2[tid] += sh2[tid+o]; }
            __syncthreads();
        }
        if (tid == 0){
            int dn = g_doneS[slot][b];
            s_alpha = dn ? 0.f : sh[0]/(sh2[0] + 1e-12f);
        }
    }
    __syncthreads();
    float al = s_alpha;

    const float* xp = xsrc + z*NPIX;
    const float* pp = psrc + z*NPIX;
    const float* tp = tsrc + z*NPIX;
    const float* tq = tpsrc + z*NPIX;
    float* xo = xdst + z*NPIX;
    float* to = tdst + z*NPIX;

    // st = tx + al*Kp (write interior to tdst)
    for (int row = ty_; row < 54; row += 8){
        int gy = Y0 - 11 + row;
        bool iny = (unsigned)gy < HV;
        for (int col = tx_; col < 54; col += 32){
            int gx = X0 - 11 + col;
            float v = 0.f;
            if (iny && (unsigned)gx < WV){
                int gi = gy*WV + gx;
                v = first ? tp[gi] : fmaf(al, tq[gi], tp[gi]);
                if (row >= 11 && row < 43 && col >= 11 && col < 43) to[gi] = v;
            }
            st[row][col] = v;
        }
    }
    // sx = x + al*p (write interior to xdst)
    for (int row = ty_; row < 40; row += 8){
        int gy = Y0 - 4 + row;
        bool iny = (unsigned)gy < HV;
        for (int col = tx_; col < 40; col += 32){
            int gx = X0 - 4 + col;
            float v = 0.f;
            if (iny && (unsigned)gx < WV){
                int gi = gy*WV + gx;
                v = first ? xp[gi] : fmaf(al, pp[gi], xp[gi]);
                if (row >= 4 && row < 36 && col >= 4 && col < 36) xo[gi] = v;
            }
            sx[row][col] = v;
        }
    }
    const float* kb = kern + b*225;
    for (int i = tid; i < 225; i += 256) sk[i] = kb[224 - i];
    for (int i = tid; i < 46*46; i += 256) (&su[0][0])[i] = 0.f;
    __syncthreads();

    // data term: su += bank6T_n(2w * bank6_n(st)), in-image zero padding
    for (int n = 0; n < 6; n++){
        float w2 = g_dkw2[stage][n];
        if (w2 == 0.f) continue;
        int nt = g_dknt[stage][n];
        if (tid < nt){
            int dy = g_dkdy[stage][n][tid], dx = g_dkdx[stage][n][tid];
            tv[tid] = g_dkv[stage][n][tid];
            oA[tid] = dy*54 + dx;
            oB[tid] = (4-dy)*50 + (4-dx);
        }
        __syncthreads();
        for (int row = ty_; row < 50; row += 8){
            int gy = Y0 - 9 + row;
            bool iny = (unsigned)gy < HV;
            for (int col = tx_; col < 50; col += 32){
                int gx = X0 - 9 + col;
                float a = 0.f;
                if (iny && (unsigned)gx < WV){
                    const float* bp = &st[row][col];
                    for (int t = 0; t < nt; t++) a = fmaf(tv[t], bp[oA[t]], a);
                    a *= w2;
                }
                sbuf[row*50+col] = a;
            }
        }
        __syncthreads();
        for (int row = ty_; row < 46; row += 8){
            int gy = Y0 - 7 + row;
            bool iny = (unsigned)gy < HV;
            for (int col = tx_; col < 46; col += 32){
                int gx = X0 - 7 + col;
                if (iny && (unsigned)gx < WV){
                    float a = su[row][col];
                    const float* bp = sbuf + row*50 + col;
                    for (int t = 0; t < nt; t++) a = fmaf(tv[t], bp[oB[t]], a);
                    su[row][col] = a;
                }
            }
        }
        __syncthreads();
    }

    // K^T 15x15 on su
    float acc[4] = {0.f,0.f,0.f,0.f};
    int rbase = ty_*4;
    for (int v = 0; v < 15; v++){
        float win[18];
        #pragma unroll
        for (int j = 0; j < 18; j++) win[j] = su[rbase+j][tx_+v];
        #pragma unroll
        for (int u = 0; u < 15; u++){
            float kv = sk[u*15+v];
            #pragma unroll
            for (int q = 0; q < 4; q++) acc[q] = fmaf(kv, win[u+q], acc[q]);
        }
    }

    // reg term: acc += bank5T_m(rkw*rpow*phi(bank5_m(x') - tgt)); writes v
    for (int m = 0; m < 5; m++){
        float wm = rkw[stage*5+m];
        float pm = rpow[stage*5+m];
        int nt = g_rknt[stage][m];
        __syncthreads();
        if (tid < nt){
            int dy = g_rkdy[stage][m][tid], dx = g_rkdx[stage][m][tid];
            tv[tid] = g_rkv[stage][m][tid];
            oA[tid] = dy*40 + dx;
            oB[tid] = (4-dy)*36 + (4-dx);
        }
        __syncthreads();
        for (int row = ty_; row < 36; row += 8){
            int gy = Y0 - 2 + row;
            bool iny = (unsigned)gy < HV;
            for (int col = tx_; col < 36; col += 32){
                int gx = X0 - 2 + col;
                float ph = 0.f;
                if (iny && (unsigned)gx < WV){
                    float vv = 0.f;
                    const float* bp = &sx[row][col];
                    for (int t = 0; t < nt; t++) vv = fmaf(tv[t], bp[oA[t]], vv);
                    int gi = (b*5+m)*CN + c*NPIX + gy*WV + gx;
                    if (tgt) vv -= tgt[gi];
                    ph = wm*pm*sgnf(vv)*powx(fabsf(vv)+EPSF, pm-1.f);
                    if (row >= 2 && row < 34 && col >= 2 && col < 34) vdst[gi] = vv;
                }
                sbuf[row*36+col] = ph;
            }
        }
        __syncthreads();
        #pragma unroll
        for (int q = 0; q < 4; q++){
            const float* bp = sbuf + (rbase+q)*36 + tx_;
            float a = acc[q];
            for (int t = 0; t < nt; t++) a = fmaf(tv[t], bp[oB[t]], a);
            acc[q] = a;
        }
    }

    // write r and partR partial
    float* ro = rdst + z*NPIX;
    float ss = 0.f;
    #pragma unroll
    for (int q = 0; q < 4; q++){
        ro[(Y0+rbase+q)*WV + X0 + tx_] = -acc[q];
        ss = fmaf(acc[q], acc[q], ss);
    }
    __syncthreads();
    sh[tid] = ss; __syncthreads();
    for (int o = 128; o; o >>= 1){ if (tid < o) sh[tid] += sh[tid+o]; __syncthreads(); }
    if (tid == 0) g_partR[b*768 + c*256 + blockIdx.y*16 + blockIdx.x] = sh[0];
}

// ---------------- prior targets ----------------
__global__ void __launch_bounds__(256)
k_prior(const float* __restrict__ xsrc, float* __restrict__ dst,
        const float* __restrict__ thr, int stage)
{
    int z = blockIdx.z; int b = z/CV, c = z - b*CV;
    __shared__ float sxx[36*36];
    int tx_ = threadIdx.x, ty_ = threadIdx.y;
    int tid = ty_*32 + tx_;
    int X0 = blockIdx.x*32, Y0 = blockIdx.y*32;
    const float* xp = xsrc + z*NPIX;
    for (int row = ty_; row < 36; row += 8){
        int gy = Y0-2+row;
        bool iny = (unsigned)gy < HV;
        for (int col = tx_; col < 36; col += 32){
            int gx = X0-2+col;
            sxx[row*36+col] = (iny && (unsigned)gx < WV) ? xp[gy*WV+gx] : 0.f;
        }
    }
    __syncthreads();
    int rbase = ty_*4;
    int gx = X0 + tx_;
    for (int m = 0; m < 5; m++){
        int nt = g_rknt[stage][m];
        float th = thr[m];
        for (int q = 0; q < 4; q++){
            int i = rbase + q;
            int base = i*36 + tx_;
            float v = 0.f;
            for (int t = 0; t < nt; t++)
                v = fmaf(g_rkv[stage][m][t], sxx[base + g_rkdy[stage][m][t]*36 + g_rkdx[stage][m][t]], v);
            dst[(b*5+m)*CN + c*NPIX + (Y0+i)*WV + gx] = sgnf(v)*fmaxf(fabsf(v)-th, 0.f);
        }
    }
}

// ---------------- bilateral grid ----------------
__global__ void k_splat(const float* __restrict__ x, float* __restrict__ grid){
    int cell = blockIdx.x*blockDim.x + threadIdx.x;
    if (cell >= BV*CV*GH*GW) return;
    int gx = cell & 63;
    int gy = (cell >> 6) & 63;
    int pc = cell >> 12;
    const float* xp = x + pc*NPIX;
    float bv[NBIN], bw[NBIN];
    #pragma unroll
    for (int z = 0; z < NBIN; z++){ bv[z] = 0.f; bw[z] = 0.f; }
    for (int dy = 0; dy < 8; dy++)
        for (int dx = 0; dx < 8; dx++){
            float I = xp[(gy*8+dy)*WV + gx*8+dx];
            float Ic = fminf(fmaxf(I, 0.f), 1.f);
            int zi = (int)rintf(Ic * (float)(NBIN-1));
            zi = max(0, min(NBIN-1, zi));
            bv[zi] += Ic; bw[zi] += 1.f;
        }
    float* gp = grid + (long)cell*NBIN*2;
    #pragma unroll
    for (int z = 0; z < NBIN; z++){ gp[z*2] = bv[z]; gp[z*2+1] = bw[z]; }
}

__global__ void k_convax(const float* __restrict__ in, float* __restrict__ out,
                         const float* __restrict__ f, int taps, int axis)
{
    int e = blockIdx.x*blockDim.x + threadIdx.x;
    if (e >= NGRID) return;
    int r = taps / 2;
    int z = (e >> 1) % NBIN;
    int cellxy = e / (2*NBIN);
    int gx = cellxy & 63;
    int gy = (cellxy >> 6) & 63;
    int coord, extent, stride;
    if (axis == 0){ coord = gy; extent = GH; stride = GW*NBIN*2; }
    else if (axis == 1){ coord = gx; extent = GW; stride = NBIN*2; }
    else { coord = z; extent = NBIN; stride = 2; }
    float s = 0.f;
    for (int t = 0; t < taps; t++){
        int cc = coord + t - r;
        if (cc >= 0 && cc < extent) s = fmaf(f[t], in[e + (cc - coord)*stride], s);
    }
    out[e] = s;
}

__global__ void k_slice(float* __restrict__ x, const float* __restrict__ grid){
    int i = blockIdx.x*blockDim.x + threadIdx.x;
    if (i >= BCN) return;
    int pc = i / NPIX;
    int pix = i - pc*NPIX;
    int y = pix / WV, xx = pix - y*WV;
    float I = x[i];
    float Ic = fminf(fmaxf(I, 0.f), 1.f);
    float yf = (float)y * 0.125f;
    float xf = (float)xx * 0.125f;
    float zf = Ic * (float)(NBIN-1);
    int y0 = max(0, min(GH-1, (int)floorf(yf)));  int y1 = min(y0+1, GH-1);
    float wy = fminf(fmaxf(yf - (float)y0, 0.f), 1.f);
    int x0 = max(0, min(GW-1, (int)floorf(xf)));  int x1 = min(x0+1, GW-1);
    float wx = fminf(fmaxf(xf - (float)x0, 0.f), 1.f);
    int z0 = max(0, min(NBIN-1, (int)floorf(zf))); int z1 = min(z0+1, NBIN-1);
    float wz = fminf(fmaxf(zf - (float)z0, 0.f), 1.f);
    const float* gp = grid + (long)pc*GH*GW*NBIN*2;
    float a0 = 0.f, a1 = 0.f;
    int ys[2]   = {y0, y1};  float wys[2] = {1.f-wy, wy};
    int xs[2]   = {x0, x1};  float wxs[2] = {1.f-wx, wx};
    int zs[2]   = {z0, z1};  float wzs[2] = {1.f-wz, wz};
    for (int a = 0; a < 2; a++)
        for (int bb = 0; bb < 2; bb++)
            for (int cc = 0; cc < 2; cc++){
                float w = wys[a]*wxs[bb]*wzs[cc];
                int idx = (((ys[a]*GW) + xs[bb])*NBIN + zs[cc])*2;
                a0 = fmaf(w, gp[idx], a0);
                a1 = fmaf(w, gp[idx+1], a1);
            }
    x[i] = a0 / (a1 + 1e-8f);
}

// ---------------- host orchestration ----------------
extern "C" void kernel_launch(void* const* d_in, const int* in_sizes, int n_in,
                              void* d_out, int out_size)
{
    const float* blurred = (const float*)d_in[0];
    const float* kern    = (const float*)d_in[1];
    const float* dks     = (const float*)d_in[2];
    const float* dkw     = (const float*)d_in[3];
    const float* rks     = (const float*)d_in[4];
    const float* rkw     = (const float*)d_in[5];
    const float* rpow    = (const float*)d_in[6];
    const float* fs      = (const float*)d_in[7];
    const float* fr      = (const float*)d_in[8];
    const float* thr     = (const float*)d_in[9];
    const int NCG = 5;

    float *px, *px2, *pr, *pp, *pt, *pt2, *ptp, *pv, *ptg, *pgA, *pgB;
    cudaGetSymbolAddress((void**)&px,  g_x);
    cudaGetSymbolAddress((void**)&px2, g_x2);
    cudaGetSymbolAddress((void**)&pr,  g_r);
    cudaGetSymbolAddress((void**)&pp,  g_p);
    cudaGetSymbolAddress((void**)&pt,  g_t);
    cudaGetSymbolAddress((void**)&pt2, g_t2);
    cudaGetSymbolAddress((void**)&ptp, g_tp);
    cudaGetSymbolAddress((void**)&pv,  g_v);
    cudaGetSymbolAddress((void**)&ptg, g_tgt);
    cudaGetSymbolAddress((void**)&pgA, g_gridA);
    cudaGetSymbolAddress((void**)&pgB, g_gridB);

    dim3 cb(32, 8);
    dim3 cg15(16, 8, BV*CV);   // 32x64 tiles
    dim3 cg32(16, 16, BV*CV);  // 32x32 tiles
    int EW = (BCN + 255)/256;

    k_prep<<<1,32>>>(dks, dkw, rks);
    k_copy<<<EW,256>>>(px, blurred, BCN);

    // one CG solve; returns buffer holding final x (updates xcur/tcur by ping-pong)
    auto cgrun = [&](int stage, const float* tgt, float* xin) -> float* {
        float* xcur = xin;            float* xnxt = (xin == px) ? px2 : px;
        float* tcur = pt;             float* tnxt = pt2;
        k_conv15<<<cg15,cb>>>(xcur, tcur, kern, blurred, 0, 0);     // t = Kx - b
        k_gradfull<<<cg32,cb>>>(xcur, pp, tcur, ptp, xnxt, tnxt, tgt, pr, pv,
                                kern, rkw, rpow, stage, 0, 1);      // first: alpha=0
        { float* tmp = xcur; xcur = xnxt; xnxt = tmp; }
        { float* tmp = tcur; tcur = tnxt; tnxt = tmp; }
        for (int it = 0; it < NCG; it++){
            int rs = it & 1;           // dotp read slot
            int ws = rs ^ 1;           // slot written by dotp, read by den/gradfull
            k_dotp<<<dim3(256,BV),256>>>(it == 0, rs);
            k_conv15<<<cg15,cb>>>(pp, ptp, kern, nullptr, 1, ws);   // Kp
            k_den<<<cg32,cb>>>(ptp, pp, pv, rkw, rpow, stage, ws);
            k_gradfull<<<cg32,cb>>>(xcur, pp, tcur, ptp, xnxt, tnxt, tgt, pr, pv,
                                    kern, rkw, rpow, stage, ws, 0);
            { float* tmp = xcur; xcur = xnxt; xnxt = tmp; }
            { float* tmp = tcur; tcur = tnxt; tnxt = tmp; }
        }
        return xcur;
    };

    float* xs0 = cgrun(0, nullptr, px);

    // bilateral grid (in place on xs0)
    k_splat<<<(BV*CV*GH*GW + 255)/256, 256>>>(xs0, pgA);
    int NGE = (NGRID + 255)/256;
    k_convax<<<NGE,256>>>(pgA, pgB, fs, 11, 0);
    k_convax<<<NGE,256>>>(pgB, pgA, fs, 11, 1);
    k_convax<<<NGE,256>>>(pgA, pgB, fr, 5, 2);
    k_slice<<<EW,256>>>(xs0, pgB);

    k_prior<<<cg32,cb>>>(xs0, ptg, thr, 1);
    float* xs1 = cgrun(1, ptg, xs0);

    k_copy<<<EW,256>>>((float*)d_out, xs1, BCN);
}

// round 6
// speedup vs baseline: 2.8320x; 1.3177x over previous
#include <cuda_runtime.h>

#define BV 2
#define CV 3
#define HV 512
#define WV 512
#define NPIX (HV*WV)
#define CN (CV*NPIX)
#define BCN (BV*CN)
#define GH 64
#define GW 64
#define NBIN 9
#define NGRID (BV*CV*GH*GW*NBIN*2)
#define EPSF 1e-8f
#define CG_TOL 1e-4f

// ---------------- scratch (device globals; no allocation) ----------------
__device__ float g_x[BCN], g_x2[BCN];
__device__ float g_r[BCN];
__device__ float g_p[BCN], g_p2[BCN];
__device__ float g_t[BCN], g_t2[BCN];
__device__ float g_tp[BCN];
__device__ float g_v[BV*5*CN];
__device__ float g_tgt[BV*5*CN];
__device__ float g_gridA[NGRID], g_gridB[NGRID];
__device__ float g_partN[BV*384];
__device__ float g_partD[BV*768];
__device__ float g_partR[BV*768];
__device__ float g_r0[BV];
__device__ float g_rnS[2][BV];
__device__ int   g_doneS[2][BV];

// sparse tap metadata, zero-padded (exact: fmaf(0,x,a)==a for finite x)
__device__ int   g_dknt[2][6];
__device__ int   g_dkdy[2][6][25];
__device__ int   g_dkdx[2][6][25];
__device__ float g_dkv [2][6][25];
__device__ float g_dkw2[2][6];
__device__ int   g_rknt[2][5];
__device__ int   g_rkdy[2][5][25];
__device__ int   g_rkdx[2][5][25];
__device__ float g_rkv [2][5][25];

__device__ __forceinline__ float powx(float a, float e){
    if (e == 0.0f) return 1.0f;
    if (e == 1.0f) return a;
    return powf(a, e);
}
__device__ __forceinline__ float sgnf(float v){
    return (v > 0.f) ? 1.f : ((v < 0.f) ? -1.f : 0.f);
}

// 4-tap register pack
struct T4 { float v0,v1,v2,v3; int o0,o1,o2,o3; };
__device__ __forceinline__ T4 t4_fwd_dk(int s,int n,int st){
    T4 t;
    t.v0=g_dkv[s][n][0]; t.v1=g_dkv[s][n][1]; t.v2=g_dkv[s][n][2]; t.v3=g_dkv[s][n][3];
    t.o0=g_dkdy[s][n][0]*st+g_dkdx[s][n][0]; t.o1=g_dkdy[s][n][1]*st+g_dkdx[s][n][1];
    t.o2=g_dkdy[s][n][2]*st+g_dkdx[s][n][2]; t.o3=g_dkdy[s][n][3]*st+g_dkdx[s][n][3];
    return t;
}
__device__ __forceinline__ T4 t4_adj_dk(int s,int n,int st){
    T4 t;
    t.v0=g_dkv[s][n][0]; t.v1=g_dkv[s][n][1]; t.v2=g_dkv[s][n][2]; t.v3=g_dkv[s][n][3];
    t.o0=(4-g_dkdy[s][n][0])*st+(4-g_dkdx[s][n][0]); t.o1=(4-g_dkdy[s][n][1])*st+(4-g_dkdx[s][n][1]);
    t.o2=(4-g_dkdy[s][n][2])*st+(4-g_dkdx[s][n][2]); t.o3=(4-g_dkdy[s][n][3])*st+(4-g_dkdx[s][n][3]);
    return t;
}
__device__ __forceinline__ T4 t4_fwd_rk(int s,int m,int st){
    T4 t;
    t.v0=g_rkv[s][m][0]; t.v1=g_rkv[s][m][1]; t.v2=g_rkv[s][m][2]; t.v3=g_rkv[s][m][3];
    t.o0=g_rkdy[s][m][0]*st+g_rkdx[s][m][0]; t.o1=g_rkdy[s][m][1]*st+g_rkdx[s][m][1];
    t.o2=g_rkdy[s][m][2]*st+g_rkdx[s][m][2]; t.o3=g_rkdy[s][m][3]*st+g_rkdx[s][m][3];
    return t;
}
__device__ __forceinline__ T4 t4_adj_rk(int s,int m,int st){
    T4 t;
    t.v0=g_rkv[s][m][0]; t.v1=g_rkv[s][m][1]; t.v2=g_rkv[s][m][2]; t.v3=g_rkv[s][m][3];
    t.o0=(4-g_rkdy[s][m][0])*st+(4-g_rkdx[s][m][0]); t.o1=(4-g_rkdy[s][m][1])*st+(4-g_rkdx[s][m][1]);
    t.o2=(4-g_rkdy[s][m][2])*st+(4-g_rkdx[s][m][2]); t.o3=(4-g_rkdy[s][m][3])*st+(4-g_rkdx[s][m][3]);
    return t;
}
__device__ __forceinline__ float c4(const float* p, const T4& t, float a){
    a = fmaf(t.v0, p[t.o0], a);
    a = fmaf(t.v1, p[t.o1], a);
    a = fmaf(t.v2, p[t.o2], a);
    a = fmaf(t.v3, p[t.o3], a);
    return a;
}
// generic fallbacks (nt > 4)
__device__ __forceinline__ float cg_fwd_dk(const float* p,int s,int n,int nt,int st,float a){
    for (int t = 0; t < nt; t++) a = fmaf(g_dkv[s][n][t], p[g_dkdy[s][n][t]*st+g_dkdx[s][n][t]], a);
    return a;
}
__device__ __forceinline__ float cg_adj_dk(const float* p,int s,int n,int nt,int st,float a){
    for (int t = 0; t < nt; t++) a = fmaf(g_dkv[s][n][t], p[(4-g_dkdy[s][n][t])*st+(4-g_dkdx[s][n][t])], a);
    return a;
}
__device__ __forceinline__ float cg_fwd_rk(const float* p,int s,int m,int nt,int st,float a){
    for (int t = 0; t < nt; t++) a = fmaf(g_rkv[s][m][t], p[g_rkdy[s][m][t]*st+g_rkdx[s][m][t]], a);
    return a;
}
__device__ __forceinline__ float cg_adj_rk(const float* p,int s,int m,int nt,int st,float a){
    for (int t = 0; t < nt; t++) a = fmaf(g_rkv[s][m][t], p[(4-g_rkdy[s][m][t])*st+(4-g_rkdx[s][m][t])], a);
    return a;
}

// ---------------- prep ----------------
__global__ void k_prep(const float* __restrict__ dks, const float* __restrict__ dkw,
                       const float* __restrict__ rks)
{
    if (threadIdx.x != 0 || blockIdx.x != 0) return;
    for (int s = 0; s < 2; s++){
        for (int n = 0; n < 6; n++){
            g_dkw2[s][n] = 2.f*dkw[s*6+n];
            int cnt = 0;
            for (int j = 0; j < 25; j++){
                float v = dks[(s*6+n)*25 + j];
                if (v != 0.f){
                    g_dkdy[s][n][cnt] = j/5; g_dkdx[s][n][cnt] = j%5;
                    g_dkv [s][n][cnt] = v; cnt++;
                }
            }
            g_dknt[s][n] = cnt;
            for (int j = cnt; j < 25; j++){ g_dkdy[s][n][j]=0; g_dkdx[s][n][j]=0; g_dkv[s][n][j]=0.f; }
        }
        for (int m = 0; m < 5; m++){
            int cnt = 0;
            for (int j = 0; j < 25; j++){
                float v = rks[(s*5+m)*25 + j];
                if (v != 0.f){
                    g_rkdy[s][m][cnt] = j/5; g_rkdx[s][m][cnt] = j%5;
                    g_rkv [s][m][cnt] = v; cnt++;
                }
            }
            g_rknt[s][m] = cnt;
            for (int j = cnt; j < 25; j++){ g_rkdy[s][m][j]=0; g_rkdx[s][m][j]=0; g_rkv[s][m][j]=0.f; }
        }
    }
}

__global__ void k_copy(float* __restrict__ dst, const float* __restrict__ src, int n){
    int i = blockIdx.x*blockDim.x + threadIdx.x;
    if (i < n) dst[i] = src[i];
}

// ---------------- plain 15x15 conv - sub (init only), 32x64 tile ----------------
__global__ void __launch_bounds__(256)
k_conv15(const float* __restrict__ src, float* __restrict__ dst,
         const float* __restrict__ kern, const float* __restrict__ sub)
{
    int z = blockIdx.z; int b = z / CV;
    __shared__ float tile[78][46];
    __shared__ float sk[225];
    const float* sp = src + z*NPIX;
    int x0 = blockIdx.x*32 - 7, y0 = blockIdx.y*64 - 7;
    int tx_ = threadIdx.x, ty_ = threadIdx.y;
    int tid = ty_*32 + tx_;
    for (int row = ty_; row < 78; row += 8){
        int gy = y0 + row;
        bool iny = (unsigned)gy < HV;
        for (int col = tx_; col < 46; col += 32){
            int gx = x0 + col;
            tile[row][col] = (iny && (unsigned)gx < WV) ? sp[gy*WV+gx] : 0.f;
        }
    }
    const float* kb = kern + b*225;
    for (int i = tid; i < 225; i += 256) sk[i] = kb[i];
    __syncthreads();
    float acc[8] = {0,0,0,0,0,0,0,0};
    int rbase = ty_*8;
    for (int v = 0; v < 15; v++){
        float win[22];
        #pragma unroll
        for (int j = 0; j < 22; j++) win[j] = tile[rbase+j][tx_+v];
        #pragma unroll
        for (int u = 0; u < 15; u++){
            float kv = sk[u*15+v];
            #pragma unroll
            for (int q = 0; q < 8; q++) acc[q] = fmaf(kv, win[u+q], acc[q]);
        }
    }
    int gx = blockIdx.x*32 + tx_;
    int gyb = blockIdx.y*64 + rbase;
    #pragma unroll
    for (int q = 0; q < 8; q++){
        int oi = z*NPIX + (gyb+q)*WV + gx;
        float o = acc[q];
        if (sub) o -= sub[oi];
        dst[oi] = o;
    }
}

// ---------------- fused: beta/done logic + p update + Kp conv + num partial -------
__global__ void __launch_bounds__(256)
k_pstep(const float* __restrict__ pold, float* __restrict__ pnew,
        float* __restrict__ kp, const float* __restrict__ rsrc,
        const float* __restrict__ kern, int first, int slot)
{
    int z = blockIdx.z; int b = z/CV, c = z - b*CV;
    int tx_ = threadIdx.x, ty_ = threadIdx.y;
    int tid = ty_*32 + tx_;
    __shared__ float pn[78][46];
    __shared__ float sk[225];
    __shared__ float sh[256];
    __shared__ float s_beta;
    __shared__ int s_freeze;

    // beta / done scalar logic (redundant deterministic reduction per block)
    float a = g_partR[b*768+tid] + g_partR[b*768+256+tid] + g_partR[b*768+512+tid];
    sh[tid] = a; __syncthreads();
    for (int o = 128; o; o >>= 1){ if (tid < o) sh[tid] += sh[tid+o]; __syncthreads(); }
    if (tid == 0){
        float nrn = sh[0];
        int done_prev = first ? 0 : g_doneS[slot][b];
        float rn_prev = first ? 1.f : g_rnS[slot][b];
        float r0 = first ? nrn : g_r0[b];
        int conv_now = (!first) && (nrn < CG_TOL*r0);
        s_beta = first ? 0.f : nrn/(rn_prev + 1e-20f);
        s_freeze = first ? 0 : (done_prev | conv_now);
        if (blockIdx.x == 0 && blockIdx.y == 0 && c == 0){
            g_doneS[slot^1][b] = done_prev | conv_now;
            g_rnS[slot^1][b] = done_prev ? rn_prev : nrn;
            if (first) g_r0[b] = nrn;
        }
    }
    __syncthreads();
    int X0 = blockIdx.x*32, Y0 = blockIdx.y*64;
    if (s_freeze){
        // p frozen: copy interior forward (Kp / partN left stale; alpha forced 0 downstream)
        const float* pop = pold + z*NPIX;
        float* pno = pnew + z*NPIX;
        for (int row = ty_; row < 64; row += 8){
            int gi = (Y0+row)*WV + X0 + tx_;
            pno[gi] = pop[gi];
        }
        return;
    }
    float beta = s_beta;
    const float* rp = rsrc + z*NPIX;
    const float* pop = pold + z*NPIX;
    float* pno = pnew + z*NPIX;
    int x0 = X0 - 7, y0 = Y0 - 7;
    float s = 0.f;
    for (int row = ty_; row < 78; row += 8){
        int gy = y0 + row;
        bool iny = (unsigned)gy < HV;
        for (int col = tx_; col < 46; col += 32){
            int gx = x0 + col;
            float v = 0.f;
            if (iny && (unsigned)gx < WV){
                int gi = gy*WV + gx;
                float rv = rp[gi];
                v = first ? rv : fmaf(beta, pop[gi], rv);
                if (row >= 7 && row < 71 && col >= 7 && col < 39){
                    pno[gi] = v;
                    s = fmaf(rv, v, s);
                }
            }
            pn[row][col] = v;
        }
    }
    const float* kb = kern + b*225;
    for (int i = tid; i < 225; i += 256) sk[i] = kb[i];
    __syncthreads();
    float acc[8] = {0,0,0,0,0,0,0,0};
    int rbase = ty_*8;
    for (int v = 0; v < 15; v++){
        float win[22];
        #pragma unroll
        for (int j = 0; j < 22; j++) win[j] = pn[rbase+j][tx_+v];
        #pragma unroll
        for (int u = 0; u < 15; u++){
            float kv = sk[u*15+v];
            #pragma unroll
            for (int q = 0; q < 8; q++) acc[q] = fmaf(kv, win[u+q], acc[q]);
        }
    }
    float* ko = kp + z*NPIX;
    #pragma unroll
    for (int q = 0; q < 8; q++)
        ko[(Y0+rbase+q)*WV + X0 + tx_] = acc[q];
    sh[tid] = s; __syncthreads();
    for (int o = 128; o; o >>= 1){ if (tid < o) sh[tid] += sh[tid+o]; __syncthreads(); }
    if (tid == 0) g_partN[b*384 + c*128 + blockIdx.y*16 + blockIdx.x] = sh[0];
}

// ---------------- alpha denominator partials ----------------
__global__ void __launch_bounds__(256)
k_den(const float* __restrict__ tsrc, const float* __restrict__ pvec,
      const float* __restrict__ vsrc,
      const float* __restrict__ rkw, const float* __restrict__ rpow,
      int stage, int slot)
{
    int z = blockIdx.z; int b = z/CV, c = z - b*CV;
    if (g_doneS[slot][b]) return;
    __shared__ float stp[36*36], spp[36*36];
    __shared__ float sh[256];
    int tx_ = threadIdx.x, ty_ = threadIdx.y;
    int tid = ty_*32 + tx_;
    int X0 = blockIdx.x*32, Y0 = blockIdx.y*32;
    const float* tp = tsrc + z*NPIX;
    const float* pp = pvec + z*NPIX;
    for (int row = ty_; row < 36; row += 8){
        int gy = Y0-2+row;
        bool iny = (unsigned)gy < HV;
        for (int col = tx_; col < 36; col += 32){
            int gx = X0-2+col;
            bool in = iny && (unsigned)gx < WV;
            stp[row*36+col] = in ? tp[gy*WV+gx] : 0.f;
            spp[row*36+col] = in ? pp[gy*WV+gx] : 0.f;
        }
    }
    __syncthreads();
    float s = 0.f;
    int rbase = ty_*4;
    for (int n = 0; n < 6; n++){
        float w2 = g_dkw2[stage][n];
        if (w2 == 0.f) continue;
        int nt = g_dknt[stage][n];
        if (nt <= 4){
            T4 tf = t4_fwd_dk(stage, n, 36);
            #pragma unroll
            for (int q = 0; q < 4; q++){
                float d = c4(stp + (rbase+q)*36 + tx_, tf, 0.f);
                s = fmaf(w2*d, d, s);
            }
        } else {
            for (int q = 0; q < 4; q++){
                float d = cg_fwd_dk(stp + (rbase+q)*36 + tx_, stage, n, nt, 36, 0.f);
                s = fmaf(w2*d, d, s);
            }
        }
    }
    for (int m = 0; m < 5; m++){
        int nt = g_rknt[stage][m];
        float pmv = rpow[stage*5+m];
        float wc = rkw[stage*5+m]*pmv*(pmv-1.f);
        if (nt <= 4){
            T4 tf = t4_fwd_rk(stage, m, 36);
            #pragma unroll
            for (int q = 0; q < 4; q++){
                float rv = c4(spp + (rbase+q)*36 + tx_, tf, 0.f);
                float vv = vsrc[(b*5+m)*CN + c*NPIX + (Y0+rbase+q)*WV + X0 + tx_];
                float w = wc*powx(fabsf(vv)+EPSF, pmv-2.f);
                s = fmaf(w*rv, rv, s);
            }
        } else {
            for (int q = 0; q < 4; q++){
                float rv = cg_fwd_rk(spp + (rbase+q)*36 + tx_, stage, m, nt, 36, 0.f);
                float vv = vsrc[(b*5+m)*CN + c*NPIX + (Y0+rbase+q)*WV + X0 + tx_];
                float w = wc*powx(fabsf(vv)+EPSF, pmv-2.f);
                s = fmaf(w*rv, rv, s);
            }
        }
    }
    sh[tid] = s; __syncthreads();
    for (int o = 128; o; o >>= 1){ if (tid < o) sh[tid] += sh[tid+o]; __syncthreads(); }
    if (tid == 0) g_partD[b*768 + c*256 + blockIdx.y*16 + blockIdx.x] = sh[0];
}

// ---------------- fused gradient + x/t update + r-norm partial ----------------
__global__ void __launch_bounds__(256,4)
k_gradfull(const float* __restrict__ xsrc, const float* __restrict__ psrc,
           const float* __restrict__ tsrc, const float* __restrict__ tpsrc,
           float* __restrict__ xdst, float* __restrict__ tdst,
           const float* __restrict__ tgt, float* __restrict__ rdst,
           float* __restrict__ vdst,
           const float* __restrict__ kern,
           const float* __restrict__ rkw, const float* __restrict__ rpow,
           int stage, int slot, int first)
{
    int z = blockIdx.z; int b = z/CV, c = z - b*CV;
    int tx_ = threadIdx.x, ty_ = threadIdx.y;
    int tid = ty_*32 + tx_;
    int X0 = blockIdx.x*32, Y0 = blockIdx.y*32;

    int dn = first ? 0 : g_doneS[slot][b];
    if (dn){
        // converged: x,t unchanged -> copy forward; r/v/partR stale-but-equal
        const float* xp = xsrc + z*NPIX;
        const float* tp = tsrc + z*NPIX;
        float* xo = xdst + z*NPIX;
        float* to = tdst + z*NPIX;
        for (int row = ty_; row < 32; row += 8){
            int gi = (Y0+row)*WV + X0 + tx_;
            xo[gi] = xp[gi];
            to[gi] = tp[gi];
        }
        return;
    }

    __shared__ float st[54][54];
    __shared__ float su[46][46];
    __shared__ float sbuf[2500];
    __shared__ float sx[40][40];
    __shared__ float sk[225];
    __shared__ float sh[256];
    __shared__ float sh2[256];
    __shared__ float s_alpha;

    if (first){
        if (tid == 0) s_alpha = 0.f;
        __syncthreads();
    } else {
        float sn = (tid < 128) ? (g_partN[b*384+tid] + g_partN[b*384+128+tid] + g_partN[b*384+256+tid]) : 0.f;
        float sd = g_partD[b*768+tid] + g_partD[b*768+256+tid] + g_partD[b*768+512+tid];
        sh[tid] = sn; sh2[tid] = sd; __syncthreads();
        for (int o = 128; o; o >>= 1){
            if (tid < o){ sh[tid] += sh[tid+o]; sh2[tid] += sh2[tid+o]; }
            __syncthreads();
        }
        if (tid == 0) s_alpha = sh[0]/(sh2[0] + 1e-12f);
        __syncthreads();
    }
    float al = s_alpha;

    const float* xp = xsrc + z*NPIX;
    const float* pp = psrc + z*NPIX;
    const float* tp = tsrc + z*NPIX;
    const float* tq = tpsrc + z*NPIX;
    float* xo = xdst + z*NPIX;
    float* to = tdst + z*NPIX;

    for (int row = ty_; row < 54; row += 8){
        int gy = Y0 - 11 + row;
        bool iny = (unsigned)gy < HV;
        for (int col = tx_; col < 54; col += 32){
            int gx = X0 - 11 + col;
            float v = 0.f;
            if (iny && (unsigned)gx < WV){
                int gi = gy*WV + gx;
                v = first ? tp[gi] : fmaf(al, tq[gi], tp[gi]);
                if (row >= 11 && row < 43 && col >= 11 && col < 43) to[gi] = v;
            }
            st[row][col] = v;
        }
    }
    for (int row = ty_; row < 40; row += 8){
        int gy = Y0 - 4 + row;
        bool iny = (unsigned)gy < HV;
        for (int col = tx_; col < 40; col += 32){
            int gx = X0 - 4 + col;
            float v = 0.f;
            if (iny && (unsigned)gx < WV){
                int gi = gy*WV + gx;
                v = first ? xp[gi] : fmaf(al, pp[gi], xp[gi]);
                if (row >= 4 && row < 36 && col >= 4 && col < 36) xo[gi] = v;
            }
            sx[row][col] = v;
        }
    }
    const float* kb = kern + b*225;
    for (int i = tid; i < 225; i += 256) sk[i] = kb[224 - i];
    for (int i = tid; i < 46*46; i += 256) (&su[0][0])[i] = 0.f;
    __syncthreads();

    // data term: su += bank6T_n(2w * bank6_n(st))
    for (int n = 0; n < 6; n++){
        float w2 = g_dkw2[stage][n];
        if (w2 == 0.f) continue;
        int nt = g_dknt[stage][n];
        if (nt == 1){
            // A^T A with one tap: aligned scale with intermediate-in-image indicator
            int dy = g_dkdy[stage][n][0], dx = g_dkdx[stage][n][0];
            float vv0 = g_dkv[stage][n][0];
            float wv2 = w2*vv0*vv0;
            for (int row = ty_; row < 46; row += 8){
                int gy = Y0 - 7 + row;
                int iy = gy + 2 - dy;
                bool okr = ((unsigned)gy < HV) && ((unsigned)iy < HV);
                for (int col = tx_; col < 46; col += 32){
                    int gx = X0 - 7 + col;
                    int ix = gx + 2 - dx;
                    if (okr && (unsigned)gx < WV && (unsigned)ix < WV)
                        su[row][col] = fmaf(wv2, st[row+4][col+4], su[row][col]);
                }
            }
        } else if (nt <= 4){
            T4 tf = t4_fwd_dk(stage, n, 54);
            for (int row = ty_; row < 50; row += 8){
                int gy = Y0 - 9 + row;
                bool iny = (unsigned)gy < HV;
                for (int col = tx_; col < 50; col += 32){
                    int gx = X0 - 9 + col;
                    float a2 = 0.f;
                    if (iny && (unsigned)gx < WV) a2 = w2*c4(&st[row][col], tf, 0.f);
                    sbuf[row*50+col] = a2;
                }
            }
            __syncthreads();
            T4 ta = t4_adj_dk(stage, n, 50);
            for (int row = ty_; row < 46; row += 8){
                int gy = Y0 - 7 + row;
                bool iny = (unsigned)gy < HV;
                for (int col = tx_; col < 46; col += 32){
                    int gx = X0 - 7 + col;
                    if (iny && (unsigned)gx < WV)
                        su[row][col] = c4(sbuf + row*50 + col, ta, su[row][col]);
                }
            }
            __syncthreads();
        } else {
            for (int row = ty_; row < 50; row += 8){
                int gy = Y0 - 9 + row;
                bool iny = (unsigned)gy < HV;
                for (int col = tx_; col < 50; col += 32){
                    int gx = X0 - 9 + col;
                    float a2 = 0.f;
                    if (iny && (unsigned)gx < WV) a2 = w2*cg_fwd_dk(&st[row][col], stage, n, nt, 54, 0.f);
                    sbuf[row*50+col] = a2;
                }
            }
            __syncthreads();
            for (int row = ty_; row < 46; row += 8){
                int gy = Y0 - 7 + row;
                bool iny = (unsigned)gy < HV;
                for (int col = tx_; col < 46; col += 32){
                    int gx = X0 - 7 + col;
                    if (iny && (unsigned)gx < WV)
                        su[row][col] = cg_adj_dk(sbuf + row*50 + col, stage, n, nt, 50, su[row][col]);
                }
            }
            __syncthreads();
        }
    }
    __syncthreads();

    // K^T 15x15 on su
    float acc[4] = {0,0,0,0};
    int rbase = ty_*4;
    for (int v = 0; v < 15; v++){
        float win[18];
        #pragma unroll
        for (int j = 0; j < 18; j++) win[j] = su[rbase+j][tx_+v];
        #pragma unroll
        for (int u = 0; u < 15; u++){
            float kv = sk[u*15+v];
            #pragma unroll
            for (int q = 0; q < 4; q++) acc[q] = fmaf(kv, win[u+q], acc[q]);
        }
    }

    // reg term: acc += bank5T_m(rkw*rpow*phi(bank5_m(x') - tgt)); writes v
    for (int m = 0; m < 5; m++){
        float wm = rkw[stage*5+m];
        float pm = rpow[stage*5+m];
        float wp = wm*pm;
        int nt = g_rknt[stage][m];
        if (nt <= 4){
            T4 tf = t4_fwd_rk(stage, m, 40);
            for (int row = ty_; row < 36; row += 8){
                int gy = Y0 - 2 + row;
                bool iny = (unsigned)gy < HV;
                for (int col = tx_; col < 36; col += 32){
                    int gx = X0 - 2 + col;
                    float ph = 0.f;
                    if (iny && (unsigned)gx < WV){
                        float vv = c4(&sx[row][col], tf, 0.f);
                        int gi = (b*5+m)*CN + c*NPIX + gy*WV + gx;
                        if (tgt) vv -= tgt[gi];
                        ph = wp*sgnf(vv)*powx(fabsf(vv)+EPSF, pm-1.f);
                        if (row >= 2 && row < 34 && col >= 2 && col < 34) vdst[gi] = vv;
                    }
                    sbuf[row*36+col] = ph;
                }
            }
            __syncthreads();
            T4 ta = t4_adj_rk(stage, m, 36);
            #pragma unroll
            for (int q = 0; q < 4; q++)
                acc[q] = c4(sbuf + (rbase+q)*36 + tx_, ta, acc[q]);
            __syncthreads();
        } else {
            for (int row = ty_; row < 36; row += 8){
                int gy = Y0 - 2 + row;
                bool iny = (unsigned)gy < HV;
                for (int col = tx_; col < 36; col += 32){
                    int gx = X0 - 2 + col;
                    float ph = 0.f;
                    if (iny && (unsigned)gx < WV){
                        float vv = cg_fwd_rk(&sx[row][col], stage, m, nt, 40, 0.f);
                        int gi = (b*5+m)*CN + c*NPIX + gy*WV + gx;
                        if (tgt) vv -= tgt[gi];
                        ph = wp*sgnf(vv)*powx(fabsf(vv)+EPSF, pm-1.f);
                        if (row >= 2 && row < 34 && col >= 2 && col < 34) vdst[gi] = vv;
                    }
                    sbuf[row*36+col] = ph;
                }
            }
            __syncthreads();
            for (int q = 0; q < 4; q++)
                acc[q] = cg_adj_rk(sbuf + (rbase+q)*36 + tx_, stage, m, nt, 36, acc[q]);
            __syncthreads();
        }
    }

    float* ro = rdst + z*NPIX;
    float ss = 0.f;
    #pragma unroll
    for (int q = 0; q < 4; q++){
        ro[(Y0+rbase+q)*WV + X0 + tx_] = -acc[q];
        ss = fmaf(acc[q], acc[q], ss);
    }
    sh[tid] = ss; __syncthreads();
    for (int o = 128; o; o >>= 1){ if (tid < o) sh[tid] += sh[tid+o]; __syncthreads(); }
    if (tid == 0) g_partR[b*768 + c*256 + blockIdx.y*16 + blockIdx.x] = sh[0];
}

// ---------------- prior targets ----------------
__global__ void __launch_bounds__(256)
k_prior(const float* __restrict__ xsrc, float* __restrict__ dst,
        const float* __restrict__ thr, int stage)
{
    int z = blockIdx.z; int b = z/CV, c = z - b*CV;
    __shared__ float sxx[36*36];
    int tx_ = threadIdx.x, ty_ = threadIdx.y;
    int X0 = blockIdx.x*32, Y0 = blockIdx.y*32;
    const float* xp = xsrc + z*NPIX;
    for (int row = ty_; row < 36; row += 8){
        int gy = Y0-2+row;
        bool iny = (unsigned)gy < HV;
        for (int col = tx_; col < 36; col += 32){
            int gx = X0-2+col;
            sxx[row*36+col] = (iny && (unsigned)gx < WV) ? xp[gy*WV+gx] : 0.f;
        }
    }
    __syncthreads();
    int rbase = ty_*4;
    int gx = X0 + tx_;
    for (int m = 0; m < 5; m++){
        int nt = g_rknt[stage][m];
        float th = thr[m];
        if (nt <= 4){
            T4 tf = t4_fwd_rk(stage, m, 36);
            #pragma unroll
            for (int q = 0; q < 4; q++){
                float v = c4(sxx + (rbase+q)*36 + tx_, tf, 0.f);
                dst[(b*5+m)*CN + c*NPIX + (Y0+rbase+q)*WV + gx] = sgnf(v)*fmaxf(fabsf(v)-th, 0.f);
            }
        } else {
            for (int q = 0; q < 4; q++){
                float v = cg_fwd_rk(sxx + (rbase+q)*36 + tx_, stage, m, nt, 36, 0.f);
                dst[(b*5+m)*CN + c*NPIX + (Y0+rbase+q)*WV + gx] = sgnf(v)*fmaxf(fabsf(v)-th, 0.f);
            }
        }
    }
}

// ---------------- bilateral grid ----------------
__global__ void k_splat(const float* __restrict__ x, float* __restrict__ grid){
    int cell = blockIdx.x*blockDim.x + threadIdx.x;
    if (cell >= BV*CV*GH*GW) return;
    int gx = cell & 63;
    int gy = (cell >> 6) & 63;
    int pc = cell >> 12;
    const float* xp = x + pc*NPIX;
    float bv[NBIN], bw[NBIN];
    #pragma unroll
    for (int z = 0; z < NBIN; z++){ bv[z] = 0.f; bw[z] = 0.f; }
    for (int dy = 0; dy < 8; dy++)
        for (int dx = 0; dx < 8; dx++){
            float I = xp[(gy*8+dy)*WV + gx*8+dx];
            float Ic = fminf(fmaxf(I, 0.f), 1.f);
            int zi = (int)rintf(Ic * (float)(NBIN-1));
            zi = max(0, min(NBIN-1, zi));
            bv[zi] += Ic; bw[zi] += 1.f;
        }
    float* gp = grid + (long)cell*NBIN*2;
    #pragma unroll
    for (int z = 0; z < NBIN; z++){ gp[z*2] = bv[z]; gp[z*2+1] = bw[z]; }
}

__global__ void k_convax(const float* __restrict__ in, float* __restrict__ out,
                         const float* __restrict__ f, int taps, int axis)
{
    int e = blockIdx.x*blockDim.x + threadIdx.x;
    if (e >= NGRID) return;
    int r = taps / 2;
    int z = (e >> 1) % NBIN;
    int cellxy = e / (2*NBIN);
    int gx = cellxy & 63;
    int gy = (cellxy >> 6) & 63;
    int coord, extent, stride;
    if (axis == 0){ coord = gy; extent = GH; stride = GW*NBIN*2; }
    else if (axis == 1){ coord = gx; extent = GW; stride = NBIN*2; }
    else { coord = z; extent = NBIN; stride = 2; }
    float s = 0.f;
    for (int t = 0; t < taps; t++){
        int cc = coord + t - r;
        if (cc >= 0 && cc < extent) s = fmaf(f[t], in[e + (cc - coord)*stride], s);
    }
    out[e] = s;
}

__global__ void k_slice(float* __restrict__ x, const float* __restrict__ grid){
    int i = blockIdx.x*blockDim.x + threadIdx.x;
    if (i >= BCN) return;
    int pc = i / NPIX;
    int pix = i - pc*NPIX;
    int y = pix / WV, xx = pix - y*WV;
    float I = x[i];
    float Ic = fminf(fmaxf(I, 0.f), 1.f);
    float yf = (float)y * 0.125f;
    float xf = (float)xx * 0.125f;
    float zf = Ic * (float)(NBIN-1);
    int y0 = max(0, min(GH-1, (int)floorf(yf)));  int y1 = min(y0+1, GH-1);
    float wy = fminf(fmaxf(yf - (float)y0, 0.f), 1.f);
    int x0 = max(0, min(GW-1, (int)floorf(xf)));  int x1 = min(x0+1, GW-1);
    float wx = fminf(fmaxf(xf - (float)x0, 0.f), 1.f);
    int z0 = max(0, min(NBIN-1, (int)floorf(zf))); int z1 = min(z0+1, NBIN-1);
    float wz = fminf(fmaxf(zf - (float)z0, 0.f), 1.f);
    const float* gp = grid + (long)pc*GH*GW*NBIN*2;
    float a0 = 0.f, a1 = 0.f;
    int ys[2]   = {y0, y1};  float wys[2] = {1.f-wy, wy};
    int xs[2]   = {x0, x1};  float wxs[2] = {1.f-wx, wx};
    int zs[2]   = {z0, z1};  float wzs[2] = {1.f-wz, wz};
    for (int a = 0; a < 2; a++)
        for (int bb = 0; bb < 2; bb++)
            for (int cc = 0; cc < 2; cc++){
                float w = wys[a]*wxs[bb]*wzs[cc];
                int idx = (((ys[a]*GW) + xs[bb])*NBIN + zs[cc])*2;
                a0 = fmaf(w, gp[idx], a0);
                a1 = fmaf(w, gp[idx+1], a1);
            }
    x[i] = a0 / (a1 + 1e-8f);
}

// ---------------- host orchestration ----------------
extern "C" void kernel_launch(void* const* d_in, const int* in_sizes, int n_in,
                              void* d_out, int out_size)
{
    const float* blurred = (const float*)d_in[0];
    const float* kern    = (const float*)d_in[1];
    const float* dks     = (const float*)d_in[2];
    const float* dkw     = (const float*)d_in[3];
    const float* rks     = (const float*)d_in[4];
    const float* rkw     = (const float*)d_in[5];
    const float* rpow    = (const float*)d_in[6];
    const float* fs      = (const float*)d_in[7];
    const float* fr      = (const float*)d_in[8];
    const float* thr     = (const float*)d_in[9];
    const int NCG = 5;

    float *px, *px2, *pr, *pp, *pp2, *pt, *pt2, *ptp, *pv, *ptg, *pgA, *pgB;
    cudaGetSymbolAddress((void**)&px,  g_x);
    cudaGetSymbolAddress((void**)&px2, g_x2);
    cudaGetSymbolAddress((void**)&pr,  g_r);
    cudaGetSymbolAddress((void**)&pp,  g_p);
    cudaGetSymbolAddress((void**)&pp2, g_p2);
    cudaGetSymbolAddress((void**)&pt,  g_t);
    cudaGetSymbolAddress((void**)&pt2, g_t2);
    cudaGetSymbolAddress((void**)&ptp, g_tp);
    cudaGetSymbolAddress((void**)&pv,  g_v);
    cudaGetSymbolAddress((void**)&ptg, g_tgt);
    cudaGetSymbolAddress((void**)&pgA, g_gridA);
    cudaGetSymbolAddress((void**)&pgB, g_gridB);

    dim3 cb(32, 8);
    dim3 cg15(16, 8, BV*CV);   // 32x64 tiles
    dim3 cg32(16, 16, BV*CV);  // 32x32 tiles
    int EW = (BCN + 255)/256;

    k_prep<<<1,32>>>(dks, dkw, rks);
    k_copy<<<EW,256>>>(px, blurred, BCN);

    auto cgrun = [&](int stage, const float* tgt, float* xin) -> float* {
        float* xcur = xin;  float* xnxt = (xin == px) ? px2 : px;
        float* tcur = pt;   float* tnxt = pt2;
        float* pcur = pp;   float* pnxt = pp2;
        k_conv15<<<cg15,cb>>>(xcur, tcur, kern, blurred);            // t = Kx - b
        k_gradfull<<<cg32,cb>>>(xcur, pcur, tcur, ptp, xnxt, tnxt, tgt, pr, pv,
                                kern, rkw, rpow, stage, 0, 1);       // first: alpha=0
        { float* q = xcur; xcur = xnxt; xnxt = q; }
        { float* q = tcur; tcur = tnxt; tnxt = q; }
        for (int it = 0; it < NCG; it++){
            int rs = it & 1, ws = rs ^ 1;
            k_pstep<<<cg15,cb>>>(pcur, pnxt, ptp, pr, kern, it == 0, rs);
            k_den<<<cg32,cb>>>(ptp, pnxt, pv, rkw, rpow, stage, ws);
            k_gradfull<<<cg32,cb>>>(xcur, pnxt, tcur, ptp, xnxt, tnxt, tgt, pr, pv,
                                    kern, rkw, rpow, stage, ws, 0);
            { float* q = xcur; xcur = xnxt; xnxt = q; }
            { float* q = tcur; tcur = tnxt; tnxt = q; }
            { float* q = pcur; pcur = pnxt; pnxt = q; }
        }
        return xcur;
    };

    float* xs0 = cgrun(0, nullptr, px);

    k_splat<<<(BV*CV*GH*GW + 255)/256, 256>>>(xs0, pgA);
    int NGE = (NGRID + 255)/256;
    k_convax<<<NGE,256>>>(pgA, pgB, fs, 11, 0);
    k_convax<<<NGE,256>>>(pgB, pgA, fs, 11, 1);
    k_convax<<<NGE,256>>>(pgA, pgB, fr, 5, 2);
    k_slice<<<EW,256>>>(xs0, pgB);

    k_prior<<<cg32,cb>>>(xs0, ptg, thr, 1);
    float* xs1 = cgrun(1, ptg, xs0);

    k_copy<<<EW,256>>>((float*)d_out, xs1, BCN);
}